// round 15
// baseline (speedup 1.0000x reference)
#include <cuda_runtime.h>
#include <cuda_bf16.h>
#include <math_constants.h>
#include <cstdint>

#define NN_  8192
#define DIN_ 1024
#define DD_  256
#define KT_  30
#define KS_  40     // screened candidates per row
#define KA3_ 768    // 3-term split of K=256
#define KAX3_ 3072  // 3-term split of K=1024

// ---------------- scratch ----------------------------------------------------
__device__ __nv_bfloat16 g_P[(size_t)NN_ * NN_];   // hi-only screening logits (128 MB)
__device__ float g_eh[NN_ * DD_];
__device__ float g_et[NN_ * DD_];
__device__ float g_E1[NN_ * DD_];
__device__ float g_spill[NN_ * DD_];
__device__ __nv_bfloat16 g_Xbf [(size_t)NN_ * KAX3_];
__device__ __nv_bfloat16 g_h1b [(size_t)NN_ * KA3_];
__device__ __nv_bfloat16 g_hb  [(size_t)NN_ * KA3_];
__device__ __nv_bfloat16 g_ehs [(size_t)NN_ * DD_];
__device__ __nv_bfloat16 g_ets [(size_t)NN_ * DD_];
__device__ __nv_bfloat16 g_Ub  [(size_t)NN_ * KA3_];
__device__ __nv_bfloat16 g_Vb  [(size_t)NN_ * KA3_];
__device__ __nv_bfloat16 g_Wfc1b[(size_t)DD_ * KAX3_];
__device__ __nv_bfloat16 g_Wfc2b[DD_ * KA3_];
__device__ __nv_bfloat16 g_Whtb [2 * DD_ * KA3_];
__device__ __nv_bfloat16 g_Wl1b [DD_ * KA3_];
__device__ __nv_bfloat16 g_Wl2b [DD_ * KA3_];
__device__ int   g_tI[NN_ * KS_];
__device__ float g_att[NN_];
__device__ float g_red[2];
__device__ float g_part[32 * DD_];

// =================== warp-MMA helpers ========================================
__device__ __forceinline__ uint32_t smem_u32(const void* p) {
    uint32_t a;
    asm("{ .reg .u64 t; cvta.to.shared.u64 t, %1; cvt.u32.u64 %0, t; }" : "=r"(a) : "l"(p));
    return a;
}
#define SW128(off) ((off) ^ (((off) >> 3) & 0x70))
#define CP16(dst, src)    asm volatile("cp.async.cg.shared.global [%0], [%1], 16;" :: "r"(dst), "l"(src) : "memory")
#define CP_COMMIT()       asm volatile("cp.async.commit_group;" ::: "memory")

__device__ __forceinline__ void ldsm4(uint32_t* r, uint32_t addr) {
    asm volatile("ldmatrix.sync.aligned.m8n8.x4.shared.b16 {%0,%1,%2,%3}, [%4];"
        : "=r"(r[0]), "=r"(r[1]), "=r"(r[2]), "=r"(r[3]) : "r"(addr));
}
__device__ __forceinline__ void mma16816(float* d, const uint32_t* a, const uint32_t* b) {
    asm volatile("mma.sync.aligned.m16n8k16.row.col.f32.bf16.bf16.f32 "
        "{%0,%1,%2,%3}, {%4,%5,%6,%7}, {%8,%9}, {%0,%1,%2,%3};"
        : "+f"(d[0]), "+f"(d[1]), "+f"(d[2]), "+f"(d[3])
        : "r"(a[0]), "r"(a[1]), "r"(a[2]), "r"(a[3]), "r"(b[0]), "r"(b[1]));
}

// ---------------- prep --------------------------------------------------------
__global__ void __launch_bounds__(256) xsplit_kernel(const float* __restrict__ x,
                                                     __nv_bfloat16* __restrict__ X)
{
    const int r = blockIdx.x;
    const int t = threadIdx.x;
    float4 v = reinterpret_cast<const float4*>(x + (size_t)r * DIN_)[t];
    __nv_bfloat16 h0 = __float2bfloat16(v.x), h1 = __float2bfloat16(v.y);
    __nv_bfloat16 h2 = __float2bfloat16(v.z), h3 = __float2bfloat16(v.w);
    __nv_bfloat16 l0 = __float2bfloat16(v.x - __bfloat162float(h0));
    __nv_bfloat16 l1 = __float2bfloat16(v.y - __bfloat162float(h1));
    __nv_bfloat16 l2 = __float2bfloat16(v.z - __bfloat162float(h2));
    __nv_bfloat16 l3 = __float2bfloat16(v.w - __bfloat162float(h3));
    __nv_bfloat16* row = X + (size_t)r * KAX3_ + 4 * t;
    __nv_bfloat162 H01; H01.x = h0; H01.y = h1;
    __nv_bfloat162 H23; H23.x = h2; H23.y = h3;
    __nv_bfloat162 L01; L01.x = l0; L01.y = l1;
    __nv_bfloat162 L23; L23.x = l2; L23.y = l3;
    reinterpret_cast<__nv_bfloat162*>(row)[0] = H01;
    reinterpret_cast<__nv_bfloat162*>(row)[1] = H23;
    reinterpret_cast<__nv_bfloat162*>(row + DIN_)[0] = L01;
    reinterpret_cast<__nv_bfloat162*>(row + DIN_)[1] = L23;
    reinterpret_cast<__nv_bfloat162*>(row + 2 * DIN_)[0] = H01;
    reinterpret_cast<__nv_bfloat162*>(row + 2 * DIN_)[1] = H23;
}
__global__ void __launch_bounds__(256) wprep6_kernel(
    const float* __restrict__ W1, const float* __restrict__ W2,
    const float* __restrict__ W3, const float* __restrict__ W4,
    const float* __restrict__ W5, const float* __restrict__ W6,
    __nv_bfloat16* __restrict__ B1, __nv_bfloat16* __restrict__ B2,
    __nv_bfloat16* __restrict__ B3, __nv_bfloat16* __restrict__ B4,
    __nv_bfloat16* __restrict__ B5, __nv_bfloat16* __restrict__ B6)
{
    int bid = blockIdx.x;
    const float* W; __nv_bfloat16* B; int K, k;
    if (bid < 1024)      { W = W1; B = B1; K = DIN_; k = bid; }
    else {
        bid -= 1024;
        const int s = bid >> 8;
        k = bid & 255; K = DD_;
        switch (s) {
            case 0: W = W2; B = B2; break;
            case 1: W = W3; B = B3; break;
            case 2: W = W4; B = B4; break;
            case 3: W = W5; B = B5; break;
            default: W = W6; B = B6; break;
        }
    }
    const int n = threadIdx.x;
    float v = W[(size_t)k * DD_ + n];
    __nv_bfloat16 h = __float2bfloat16(v);
    __nv_bfloat16 l = __float2bfloat16(v - __bfloat162float(h));
    __nv_bfloat16* row = B + (size_t)n * (3 * K);
    row[k] = h; row[K + k] = h; row[2*K + k] = l;
}

#define MMA_STG 32768

// ---------------- tile fill, 512-thread version ------------------------------
__device__ __forceinline__ void tile_fill(uint32_t sbase, int kc, int bm, int bn,
    const __nv_bfloat16* __restrict__ Ag, const __nv_bfloat16* __restrict__ Bg,
    int tid, int Ka)
{
    #pragma unroll
    for (int i = 0; i < 2; i++) {
        int q = tid + i * 512;
        int row = q >> 3, c = q & 7;
        const __nv_bfloat16* src = Ag + (size_t)(bm * 128 + row) * Ka + kc * 64 + c * 8;
        CP16(sbase + SW128((uint32_t)(row * 128 + c * 16)), src);
    }
    #pragma unroll
    for (int i = 0; i < 2; i++) {
        int q = tid + i * 512;
        int row = q >> 3, c = q & 7;
        const __nv_bfloat16* src = Bg + (size_t)(bn * 128 + row) * Ka + kc * 64 + c * 8;
        CP16(sbase + 16384 + SW128((uint32_t)(row * 128 + c * 16)), src);
    }
}
// ---------------- tile fill, 256-thread version ------------------------------
__device__ __forceinline__ void tile_fill8(uint32_t sbase, int kc, int bm, int bn,
    const __nv_bfloat16* __restrict__ Ag, const __nv_bfloat16* __restrict__ Bg,
    int tid, int Ka)
{
    #pragma unroll
    for (int i = 0; i < 4; i++) {
        int q = tid + i * 256;
        int row = q >> 3, c = q & 7;
        const __nv_bfloat16* src = Ag + (size_t)(bm * 128 + row) * Ka + kc * 64 + c * 8;
        CP16(sbase + SW128((uint32_t)(row * 128 + c * 16)), src);
    }
    #pragma unroll
    for (int i = 0; i < 4; i++) {
        int q = tid + i * 256;
        int row = q >> 3, c = q & 7;
        const __nv_bfloat16* src = Bg + (size_t)(bn * 128 + row) * Ka + kc * 64 + c * 8;
        CP16(sbase + 16384 + SW128((uint32_t)(row * 128 + c * 16)), src);
    }
}

// ---------------- 16-warp mainloop (trunk GEMMs) -----------------------------
struct MmaAcc { float a[2][4][4]; };

__device__ __forceinline__ void mma_mainloop(MmaAcc& A_, uint32_t sb, int nchunk,
    int bm, int bn, const __nv_bfloat16* Ag, const __nv_bfloat16* Bg, int Ka,
    int tid, int wid, int lane)
{
    const int wm = (wid & 3) * 32;
    const int wn = (wid >> 2) * 32;
    const int aRow = (lane & 15);
    const int aKb  = (lane >> 4) * 16;
    const int bRow = ((lane >> 4) << 3) + (lane & 7);
    const int bKb  = ((lane >> 3) & 1) * 16;

    uint32_t aOff[2], bOff[2];
    aOff[0] = SW128((uint32_t)((wm +      aRow) * 128 + aKb));
    aOff[1] = SW128((uint32_t)((wm + 16 + aRow) * 128 + aKb));
    bOff[0] = SW128((uint32_t)((wn +      bRow) * 128 + bKb)) + 16384u;
    bOff[1] = SW128((uint32_t)((wn + 16 + bRow) * 128 + bKb)) + 16384u;

    tile_fill(sb,           0, bm, bn, Ag, Bg, tid, Ka);
    CP_COMMIT();
    tile_fill(sb + MMA_STG, 1, bm, bn, Ag, Bg, tid, Ka);
    CP_COMMIT();

    int sidx = 0;
    for (int c = 0; c < nchunk; c++) {
        asm volatile("cp.async.wait_group 1;" ::: "memory");
        __syncthreads();

        if (c + 2 < nchunk) {
            int s2 = sidx + 2; if (s2 >= 3) s2 -= 3;
            tile_fill(sb + s2 * MMA_STG, c + 2, bm, bn, Ag, Bg, tid, Ka);
            CP_COMMIT();
        }

        const uint32_t stg = sb + sidx * MMA_STG;
        uint32_t abuf[2][2][4], bbuf[2][2][4];
        ldsm4(abuf[0][0], stg + aOff[0]);
        ldsm4(abuf[0][1], stg + aOff[1]);
        ldsm4(bbuf[0][0], stg + bOff[0]);
        ldsm4(bbuf[0][1], stg + bOff[1]);
        #pragma unroll
        for (int ks = 0; ks < 4; ks++) {
            const int cur = ks & 1, nxt = cur ^ 1;
            if (ks < 3) {
                const uint32_t x = (uint32_t)(ks + 1) << 5;
                ldsm4(abuf[nxt][0], (stg + aOff[0]) ^ x);
                ldsm4(abuf[nxt][1], (stg + aOff[1]) ^ x);
                ldsm4(bbuf[nxt][0], (stg + bOff[0]) ^ x);
                ldsm4(bbuf[nxt][1], (stg + bOff[1]) ^ x);
            }
            #pragma unroll
            for (int mt = 0; mt < 2; mt++)
                #pragma unroll
                for (int n8 = 0; n8 < 4; n8++)
                    mma16816(A_.a[mt][n8], abuf[cur][mt], &bbuf[cur][n8 >> 1][(n8 & 1) * 2]);
        }
        if (++sidx == 3) sidx = 0;
    }
}

// ---------------- 8-warp mainloop (attn GEMM, 2 CTA/SM) ----------------------
struct MmaAcc8 { float a[2][8][4]; };

__device__ __forceinline__ void mma_mainloop8(MmaAcc8& A_, uint32_t sb, int nchunk,
    int bm, int bn, const __nv_bfloat16* Ag, const __nv_bfloat16* Bg, int Ka,
    int tid, int wid, int lane)
{
    const int wm = (wid & 3) * 32;
    const int wn = (wid >> 2) * 64;
    const int aRow = (lane & 15);
    const int aKb  = (lane >> 4) * 16;
    const int bRow = ((lane >> 4) << 3) + (lane & 7);
    const int bKb  = ((lane >> 3) & 1) * 16;

    uint32_t aOff[2], bOff[4];
    aOff[0] = SW128((uint32_t)((wm +      aRow) * 128 + aKb));
    aOff[1] = SW128((uint32_t)((wm + 16 + aRow) * 128 + aKb));
    #pragma unroll
    for (int nt = 0; nt < 4; nt++)
        bOff[nt] = SW128((uint32_t)((wn + nt * 16 + bRow) * 128 + bKb)) + 16384u;

    tile_fill8(sb,           0, bm, bn, Ag, Bg, tid, Ka);
    CP_COMMIT();
    tile_fill8(sb + MMA_STG, 1, bm, bn, Ag, Bg, tid, Ka);
    CP_COMMIT();

    int sidx = 0;
    for (int c = 0; c < nchunk; c++) {
        asm volatile("cp.async.wait_group 1;" ::: "memory");
        __syncthreads();

        if (c + 2 < nchunk) {
            int s2 = sidx + 2; if (s2 >= 3) s2 -= 3;
            tile_fill8(sb + s2 * MMA_STG, c + 2, bm, bn, Ag, Bg, tid, Ka);
            CP_COMMIT();
        }

        const uint32_t stg = sb + sidx * MMA_STG;
        uint32_t abuf[2][2][4], bbuf[2][4][4];
        ldsm4(abuf[0][0], stg + aOff[0]);
        ldsm4(abuf[0][1], stg + aOff[1]);
        #pragma unroll
        for (int nt = 0; nt < 4; nt++) ldsm4(bbuf[0][nt], stg + bOff[nt]);
        #pragma unroll
        for (int ks = 0; ks < 4; ks++) {
            const int cur = ks & 1, nxt = cur ^ 1;
            if (ks < 3) {
                const uint32_t x = (uint32_t)(ks + 1) << 5;
                ldsm4(abuf[nxt][0], (stg + aOff[0]) ^ x);
                ldsm4(abuf[nxt][1], (stg + aOff[1]) ^ x);
                #pragma unroll
                for (int nt = 0; nt < 4; nt++)
                    ldsm4(bbuf[nxt][nt], (stg + bOff[nt]) ^ x);
            }
            #pragma unroll
            for (int mt = 0; mt < 2; mt++)
                #pragma unroll
                for (int n8 = 0; n8 < 8; n8++)
                    mma16816(A_.a[mt][n8], abuf[cur][mt], &bbuf[cur][n8 >> 1][(n8 & 1) * 2]);
        }
        if (++sidx == 3) sidx = 0;
    }
}

// ------- attn screening GEMM: P(bf16) = ehs @ ets^T (hi-only, K=256) ---------
__global__ void __launch_bounds__(256, 2) attn_mma_kernel(
    const __nv_bfloat16* __restrict__ Ag, const __nv_bfloat16* __restrict__ Bg,
    __nv_bfloat16* __restrict__ P)
{
    extern __shared__ char smem[];
    const uint32_t sb = smem_u32(smem);
    const int tid = threadIdx.x, wid = tid >> 5, lane = tid & 31;
    const int bn = blockIdx.x, bm = blockIdx.y;

    MmaAcc8 acc;
    #pragma unroll
    for (int i = 0; i < 2; i++)
        #pragma unroll
        for (int j = 0; j < 8; j++)
            #pragma unroll
            for (int q = 0; q < 4; q++) acc.a[i][j][q] = 0.f;

    mma_mainloop8(acc, sb, DD_ / 64, bm, bn, Ag, Bg, DD_, tid, wid, lane);

    const int wm = (wid & 3) * 32, wn = (wid >> 2) * 64;
    const int tig = lane & 3, gid = lane >> 2;
    #pragma unroll
    for (int mt = 0; mt < 2; mt++) {
        const int r0 = bm * 128 + wm + mt * 16 + gid;
        #pragma unroll
        for (int n8 = 0; n8 < 8; n8++) {
            const int cc = bn * 128 + wn + n8 * 8 + tig * 2;
            *reinterpret_cast<__nv_bfloat162*>(P + (size_t)r0 * NN_ + cc)
                = __floats2bfloat162_rn(acc.a[mt][n8][0], acc.a[mt][n8][1]);
            *reinterpret_cast<__nv_bfloat162*>(P + (size_t)(r0 + 8) * NN_ + cc)
                = __floats2bfloat162_rn(acc.a[mt][n8][2], acc.a[mt][n8][3]);
        }
    }
}

// ---------------- trunk GEMM with fused split epilogues ----------------------
template<int OSPL, bool RELU, bool HASADD>
__global__ void __launch_bounds__(512, 1) mma_gemm_kernel(
    const __nv_bfloat16* __restrict__ Ag, const __nv_bfloat16* __restrict__ Bg,
    const float* __restrict__ bias, const float* __restrict__ addend,
    float* __restrict__ C, __nv_bfloat16* __restrict__ S, int Ka)
{
    extern __shared__ char smem[];
    const uint32_t sb = smem_u32(smem);
    const int tid = threadIdx.x, wid = tid >> 5, lane = tid & 31;
    const int bn = blockIdx.x, bm = blockIdx.y;

    MmaAcc acc;
    #pragma unroll
    for (int i = 0; i < 2; i++)
        #pragma unroll
        for (int j = 0; j < 4; j++)
            #pragma unroll
            for (int q = 0; q < 4; q++) acc.a[i][j][q] = 0.f;

    mma_mainloop(acc, sb, Ka / 64, bm, bn, Ag, Bg, Ka, tid, wid, lane);

    const int wm = (wid & 3) * 32, wn = (wid >> 2) * 32;
    const int tig = lane & 3, gid = lane >> 2;
    #pragma unroll
    for (int mt = 0; mt < 2; mt++) {
        #pragma unroll
        for (int n8 = 0; n8 < 4; n8++) {
            const int cc = bn * 128 + wn + n8 * 8 + tig * 2;
            #pragma unroll
            for (int hh = 0; hh < 2; hh++) {
                const int r = bm * 128 + wm + mt * 16 + gid + hh * 8;
                #pragma unroll
                for (int e = 0; e < 2; e++) {
                    const int c = cc + e;
                    float v = acc.a[mt][n8][hh * 2 + e] + bias[c];
                    if (RELU)   v = fmaxf(v, 0.f);
                    if (HASADD) v += addend[(size_t)r * DD_ + c];
                    if (C) C[(size_t)r * DD_ + c] = v;
                    if (OSPL == 1) {
                        __nv_bfloat16 h = __float2bfloat16(v);
                        __nv_bfloat16 l = __float2bfloat16(v - __bfloat162float(h));
                        __nv_bfloat16* row = S + (size_t)r * KA3_;
                        row[c] = h; row[DD_ + c] = l; row[2*DD_ + c] = h;
                    }
                }
            }
        }
    }
}

// -------- fused head+tail GEMM: N=512, cols<256 -> eh/ehs, >=256 -> et/ets ----
__global__ void __launch_bounds__(512, 1) ht_gemm_kernel(
    const __nv_bfloat16* __restrict__ Ag, const __nv_bfloat16* __restrict__ Bg,
    const float* __restrict__ bhd, const float* __restrict__ btl,
    float* __restrict__ eh, float* __restrict__ et,
    __nv_bfloat16* __restrict__ ehs, __nv_bfloat16* __restrict__ ets)
{
    extern __shared__ char smem[];
    const uint32_t sb = smem_u32(smem);
    const int tid = threadIdx.x, wid = tid >> 5, lane = tid & 31;
    const int bn = blockIdx.x, bm = blockIdx.y;

    MmaAcc acc;
    #pragma unroll
    for (int i = 0; i < 2; i++)
        #pragma unroll
        for (int j = 0; j < 4; j++)
            #pragma unroll
            for (int q = 0; q < 4; q++) acc.a[i][j][q] = 0.f;

    mma_mainloop(acc, sb, KA3_ / 64, bm, bn, Ag, Bg, KA3_, tid, wid, lane);

    const int wm = (wid & 3) * 32, wn = (wid >> 2) * 32;
    const int tig = lane & 3, gid = lane >> 2;
    #pragma unroll
    for (int mt = 0; mt < 2; mt++) {
        #pragma unroll
        for (int n8 = 0; n8 < 4; n8++) {
            const int cc = bn * 128 + wn + n8 * 8 + tig * 2;
            #pragma unroll
            for (int hh = 0; hh < 2; hh++) {
                const int r = bm * 128 + wm + mt * 16 + gid + hh * 8;
                #pragma unroll
                for (int e = 0; e < 2; e++) {
                    const int c = cc + e;
                    if (c < 256) {
                        float v = acc.a[mt][n8][hh * 2 + e] + bhd[c];
                        eh [(size_t)r * DD_ + c] = v;
                        ehs[(size_t)r * DD_ + c] = __float2bfloat16(v * 0.0625f);
                    } else {
                        const int c2 = c - 256;
                        float v = acc.a[mt][n8][hh * 2 + e] + btl[c2];
                        et [(size_t)r * DD_ + c2] = v;
                        ets[(size_t)r * DD_ + c2] = __float2bfloat16(v);
                    }
                }
            }
        }
    }
}

// ---------------- per-row top-40 screening via 11-bit radix ------------------
// slot s = 8*j + e  ->  global idx = 8*(tid + j*256) + e
#define TK_CAP 512
__global__ void __launch_bounds__(256) topk_kernel(const __nv_bfloat16* __restrict__ P,
                                                   int* __restrict__ tI)
{
    const int row  = blockIdx.x;
    const int tid  = threadIdx.x;
    const int lane = tid & 31, w = tid >> 5;
    const uint4* p4 = reinterpret_cast<const uint4*>(P + (size_t)row * NN_);

    float v[32];
    uint32_t key[32];
    #pragma unroll
    for (int j = 0; j < 4; j++) {
        uint4 pk = p4[tid + j * 256];
        uint32_t ws[4] = {pk.x, pk.y, pk.z, pk.w};
        #pragma unroll
        for (int h = 0; h < 4; h++) {
            __nv_bfloat162 b2 = *reinterpret_cast<const __nv_bfloat162*>(&ws[h]);
            float2 f = __bfloat1622float2(b2);
            const int s = 8 * j + 2 * h;
            v[s]   = f.x;
            v[s+1] = f.y;
            uint32_t u0 = __float_as_uint(f.x);
            uint32_t u1 = __float_as_uint(f.y);
            key[s]   = (u0 & 0x80000000u) ? ~u0 : (u0 | 0x80000000u);
            key[s+1] = (u1 & 0x80000000u) ? ~u1 : (u1 | 0x80000000u);
        }
    }

    __shared__ int   hist[2048];
    __shared__ int   part[256];
    __shared__ int   sPivot[4];
    __shared__ float sV[KS_];
    __shared__ int   sI[KS_];
    __shared__ float cV[TK_CAP];
    __shared__ int   cI[TK_CAP];
    __shared__ int   cnts[2];

    #pragma unroll
    for (int i = 0; i < 8; i++) hist[tid * 8 + i] = 0;
    if (tid < 2) cnts[tid] = 0;
    __syncthreads();

    #pragma unroll
    for (int s = 0; s < 32; s++) atomicAdd(&hist[key[s] >> 21], 1);
    __syncthreads();

    {
        int s = 0;
        #pragma unroll
        for (int i = 0; i < 8; i++) s += hist[tid * 8 + i];
        part[tid] = s;
    }
    __syncthreads();
    if (tid == 0) {
        int acc = 0, t = 255;
        for (; t >= 0; t--) { acc += part[t]; if (acc >= KS_) break; }
        int cntAbove = acc - part[t];
        int b = -1;
        for (int bin = t * 8 + 7; bin >= t * 8; bin--) {
            int h = hist[bin];
            if (cntAbove + h >= KS_) { b = bin; break; }
            cntAbove += h;
        }
        sPivot[0] = b; sPivot[1] = cntAbove;
        sPivot[2] = 0;
    }
    __syncthreads();

    const uint32_t pb = (uint32_t)sPivot[0];
    const int nAbove  = sPivot[1];

    #pragma unroll
    for (int s = 0; s < 32; s++) {
        uint32_t bin = key[s] >> 21;
        if (bin > pb) {
            int pos = atomicAdd(&cnts[0], 1);
            sV[pos] = v[s]; sI[pos] = 8 * (tid + (s >> 3) * 256) + (s & 7);
        } else if (bin == pb) {
            int pos = atomicAdd(&cnts[1], 1);
            if (pos < TK_CAP) { cV[pos] = v[s]; cI[pos] = 8 * (tid + (s >> 3) * 256) + (s & 7); }
            else sPivot[2] = 1;
        }
    }
    __syncthreads();

    if (sPivot[2] == 0) {
        if (tid < 32) {
            const int ncand = min(cnts[1], TK_CAP);
            const int need  = KS_ - nAbove;
            float mv[16]; int mi[16];
            #pragma unroll
            for (int q = 0; q < 16; q++) {
                int idx = tid + q * 32;
                if (idx < ncand) { mv[q] = cV[idx]; mi[q] = cI[idx]; }
                else             { mv[q] = -CUDART_INF_F; mi[q] = 0x7fffffff; }
            }
            for (int it = 0; it < need; it++) {
                float bv = mv[0]; int bi = mi[0], bq = 0;
                #pragma unroll
                for (int q = 1; q < 16; q++)
                    if (mv[q] > bv || (mv[q] == bv && mi[q] < bi)) { bv = mv[q]; bi = mi[q]; bq = q; }
                float wv = bv; int wi = bi;
                #pragma unroll
                for (int off = 16; off; off >>= 1) {
                    float ov = __shfl_xor_sync(0xffffffffu, wv, off);
                    int   oi = __shfl_xor_sync(0xffffffffu, wi, off);
                    if (ov > wv || (ov == wv && oi < wi)) { wv = ov; wi = oi; }
                }
                if (bi == wi && bv == wv && bi != 0x7fffffff) {
                    sI[nAbove + it] = wi;
                    mv[bq] = -CUDART_INF_F; mi[bq] = 0x7fffffff;
                }
                __syncwarp();
            }
        }
        __syncthreads();
    } else {
        // degenerate fallback: exact iterative argmax
        __syncthreads();
        __shared__ float fV[8]; __shared__ int fI[9];
        float bv = v[0]; int bs = 0;
        #pragma unroll
        for (int s = 1; s < 32; s++) if (v[s] > bv) { bv = v[s]; bs = s; }
        for (int it = 0; it < KS_; it++) {
            float wv = bv; int wi = 8 * (tid + (bs >> 3) * 256) + (bs & 7);
            #pragma unroll
            for (int off = 16; off; off >>= 1) {
                float ov = __shfl_xor_sync(0xffffffffu, wv, off);
                int   oi = __shfl_xor_sync(0xffffffffu, wi, off);
                if (ov > wv || (ov == wv && oi < wi)) { wv = ov; wi = oi; }
            }
            if (lane == 0) { fV[w] = wv; fI[w] = wi; }
            __syncthreads();
            if (tid == 0) {
                float Bv = fV[0]; int Bi = fI[0];
                #pragma unroll
                for (int q = 1; q < 8; q++)
                    if (fV[q] > Bv || (fV[q] == Bv && fI[q] < Bi)) { Bv = fV[q]; Bi = fI[q]; }
                sI[it] = Bi; fI[8] = Bi;
            }
            __syncthreads();
            const int win = fI[8];
            if (((win >> 3) & 255) == tid) {
                v[8 * (win >> 11) + (win & 7)] = -CUDART_INF_F;
                bv = v[0]; bs = 0;
                #pragma unroll
                for (int s = 1; s < 32; s++) if (v[s] > bv) { bv = v[s]; bs = s; }
            }
        }
        __syncthreads();
    }

    if (tid < KS_) tI[row * KS_ + tid] = sI[tid];
}

// ------ fused rescore + parallel-rank exact top-30 + neighbor aggregation ----
__global__ void __launch_bounds__(256) neighbor_kernel(
    const float* __restrict__ eH, const float* __restrict__ eT,
    const int* __restrict__ tI,
    __nv_bfloat16* __restrict__ Ub, __nv_bfloat16* __restrict__ Vb)
{
    const int row  = blockIdx.x;
    const int d    = threadIdx.x;
    const int lane = d & 31, w = d >> 5;

    __shared__ __align__(16) float sNb[KS_][DD_];
    __shared__ __align__(16) float sEh[DD_];
    __shared__ float sVal[KS_];
    __shared__ int   sIdx[KS_];
    __shared__ int   sSel[KT_];
    __shared__ float sSelV[KT_];
    __shared__ float sPr[KT_];
    __shared__ float sW[KT_];
    __shared__ float sKa[KT_];

    const float eh = eH[(size_t)row * DD_ + d];
    sEh[d] = eh;
    if (d < KS_) sIdx[d] = tI[row * KS_ + d];
    __syncthreads();

    // block-wide async prefetch of all 40 candidate rows (fully parallel)
    const uint32_t nbBase = smem_u32(&sNb[0][0]);
    #pragma unroll
    for (int i = 0; i < 10; i++) {           // 40 rows x 64 float4 = 2560 copies
        const int idx = d + i * 256;
        const int k  = idx >> 6;
        const int c4 = idx & 63;
        CP16(nbBase + (uint32_t)(k * DD_ + c4 * 4) * 4u,
             eT + (size_t)sIdx[k] * DD_ + c4 * 4);
    }
    CP_COMMIT();
    asm volatile("cp.async.wait_group 0;" ::: "memory");
    __syncthreads();

    // exact fp32 rescore from smem (same value order as before)
    for (int k = w; k < KS_; k += 8) {
        const float4* src = reinterpret_cast<const float4*>(sNb[k]);
        const float4* eh4 = reinterpret_cast<const float4*>(sEh);
        float dot = 0.f;
        #pragma unroll
        for (int q = 0; q < 2; q++) {
            const int i4 = lane + q * 32;
            float4 t = src[i4];
            float4 e4 = eh4[i4];
            dot += t.x * e4.x + t.y * e4.y + t.z * e4.z + t.w * e4.w;
        }
        #pragma unroll
        for (int off = 16; off; off >>= 1) dot += __shfl_xor_sync(0xffffffffu, dot, off);
        if (lane == 0) sVal[k] = dot * 0.0625f;
    }
    __syncthreads();

    // parallel rank select: exact top-30-of-40 by (value desc, idx asc)
    if (d < KS_) {
        const float vd = sVal[d];
        const int   id = sIdx[d];
        int rank = 0;
        #pragma unroll
        for (int j = 0; j < KS_; j++) {
            const float vj = sVal[j];
            const int   ij = sIdx[j];
            if (vj > vd || (vj == vd && ij < id)) rank++;
        }
        if (rank < KT_) { sSel[rank] = d; sSelV[rank] = vd; }
    }
    __syncthreads();

    if (d < 32) {
        float ev = (d < KT_) ? expf(sSelV[d] - sSelV[0]) : 0.f;
        float s = ev;
        #pragma unroll
        for (int off = 16; off; off >>= 1) s += __shfl_xor_sync(0xffffffffu, s, off);
        if (d < KT_) sPr[d] = ev / s;
    }
    __syncthreads();

    for (int k = w; k < KT_; k += 8) {
        const int s = sSel[k];
        const float pk = sPr[k], ck = 2.f - pk;
        float snb = 0.f, sg = 0.f;
        #pragma unroll
        for (int q = 0; q < 8; q++) {
            const int dd = lane + q * 32;
            const float nb = sNb[s][dd];
            snb += nb;
            sg  += tanhf(ck * sEh[dd] + pk * nb);
        }
        #pragma unroll
        for (int off = 16; off; off >>= 1) {
            snb += __shfl_xor_sync(0xffffffffu, snb, off);
            sg  += __shfl_xor_sync(0xffffffffu, sg,  off);
        }
        if (lane == 0) sW[k] = snb * sg;
    }
    __syncthreads();

    if (d < 32) {
        float val = (d < KT_) ? sW[d] : -CUDART_INF_F;
        float m = val;
        #pragma unroll
        for (int off = 16; off; off >>= 1) m = fmaxf(m, __shfl_xor_sync(0xffffffffu, m, off));
        float ev = (d < KT_) ? expf(val - m) : 0.f;
        float s = ev;
        #pragma unroll
        for (int off = 16; off; off >>= 1) s += __shfl_xor_sync(0xffffffffu, s, off);
        if (d < KT_) sKa[d] = ev / s;
    }
    __syncthreads();

    float acc = 0.f;
    #pragma unroll
    for (int k = 0; k < KT_; k++) acc += sKa[k] * sNb[sSel[k]][d];

    const float u = eh + acc, vv = eh * acc;
    {
        __nv_bfloat16 h = __float2bfloat16(u);
        __nv_bfloat16 l = __float2bfloat16(u - __bfloat162float(h));
        __nv_bfloat16* rw = Ub + (size_t)row * KA3_;
        rw[d] = h; rw[DD_ + d] = l; rw[2*DD_ + d] = h;
    }
    {
        __nv_bfloat16 h = __float2bfloat16(vv);
        __nv_bfloat16 l = __float2bfloat16(vv - __bfloat162float(h));
        __nv_bfloat16* rw = Vb + (size_t)row * KA3_;
        rw[d] = h; rw[DD_ + d] = l; rw[2*DD_ + d] = h;
    }
}

// ---------------- attention head ----------------------------------------------
__global__ void __launch_bounds__(128) att_kernel(
    const float* __restrict__ E, const float* __restrict__ W1,
    const float* __restrict__ b1, const float* __restrict__ W2,
    const float* __restrict__ b2, float* __restrict__ att)
{
    const int r0 = blockIdx.x * 16;
    const int j  = threadIdx.x;
    __shared__ float sE[16][DD_];
    for (int t = j; t < 16 * DD_; t += 128)
        sE[t >> 8][t & 255] = E[(size_t)(r0 + (t >> 8)) * DD_ + (t & 255)];
    __syncthreads();

    float acc[16];
    #pragma unroll
    for (int r = 0; r < 16; r++) acc[r] = 0.f;
    for (int dd = 0; dd < DD_; dd++) {
        const float wv = W1[dd * 128 + j];
        #pragma unroll
        for (int r = 0; r < 16; r++) acc[r] += sE[r][dd] * wv;
    }
    const float bb = b1[j], w2 = W2[j];
    __shared__ float sRed[16][4];
    const int lane = j & 31, w = j >> 5;
    #pragma unroll
    for (int r = 0; r < 16; r++) {
        float val = acc[r] + bb;
        val = (val > 0.f) ? val : 0.01f * val;
        val *= w2;
        #pragma unroll
        for (int off = 16; off; off >>= 1) val += __shfl_xor_sync(0xffffffffu, val, off);
        if (lane == 0) sRed[r][w] = val;
    }
    __syncthreads();
    if (j < 16) att[r0 + j] = sRed[j][0] + sRed[j][1] + sRed[j][2] + sRed[j][3] + b2[0];
}

// ---------------- softmax-over-nodes reduction --------------------------------
__global__ void __launch_bounds__(1024) smred_kernel(const float* __restrict__ att,
                                                     float* __restrict__ red)
{
    const int tid = threadIdx.x;
    __shared__ float s[32];
    float m = -CUDART_INF_F;
    for (int i = tid; i < NN_; i += 1024) m = fmaxf(m, att[i]);
    #pragma unroll
    for (int off = 16; off; off >>= 1) m = fmaxf(m, __shfl_xor_sync(0xffffffffu, m, off));
    if ((tid & 31) == 0) s[tid >> 5] = m;
    __syncthreads();
    if (tid < 32) {
        float mm = s[tid];
        #pragma unroll
        for (int off = 16; off; off >>= 1) mm = fmaxf(mm, __shfl_xor_sync(0xffffffffu, mm, off));
        if (tid == 0) s[0] = mm;
    }
    __syncthreads();
    const float M = s[0];
    __syncthreads();
    float z = 0.f;
    for (int i = tid; i < NN_; i += 1024) z += expf(att[i] - M);
    #pragma unroll
    for (int off = 16; off; off >>= 1) z += __shfl_xor_sync(0xffffffffu, z, off);
    if ((tid & 31) == 0) s[tid >> 5] = z;
    __syncthreads();
    if (tid < 32) {
        float zz = s[tid];
        #pragma unroll
        for (int off = 16; off; off >>= 1) zz += __shfl_xor_sync(0xffffffffu, zz, off);
        if (tid == 0) { red[0] = M; red[1] = zz; }
    }
}

__global__ void __launch_bounds__(256) egpart_kernel(const float* __restrict__ att,
    const float* __restrict__ E, const float* __restrict__ red, float* __restrict__ part)
{
    const int b = blockIdx.x;
    const int d = threadIdx.x;
    __shared__ float wsh[256];
    wsh[d] = expf(att[b * 256 + d] - red[0]);
    __syncthreads();
    float acc = 0.f;
    const float* Eb = E + (size_t)b * 256 * DD_;
    for (int i = 0; i < 256; i++) acc += wsh[i] * Eb[(size_t)i * DD_ + d];
    part[b * DD_ + d] = acc;
}

__global__ void __launch_bounds__(256) egfin_kernel(const float* __restrict__ part,
    const float* __restrict__ red, float* __restrict__ eg)
{
    const int d = threadIdx.x;
    float s = 0.f;
    #pragma unroll
    for (int b = 0; b < 32; b++) s += part[b * DD_ + d];
    eg[d] = s / red[1];
}

// ---------------- launcher -----------------------------------------------------
extern "C" void kernel_launch(void* const* d_in, const int* in_sizes, int n_in,
                              void* d_out, int out_size)
{
    const float* x    = (const float*)d_in[0];
    const float* Wfc1 = (const float*)d_in[1];
    const float* bfc1 = (const float*)d_in[2];
    const float* Wfc2 = (const float*)d_in[3];
    const float* bfc2 = (const float*)d_in[4];
    const float* Whd  = (const float*)d_in[5];
    const float* bhd  = (const float*)d_in[6];
    const float* Wtl  = (const float*)d_in[7];
    const float* btl  = (const float*)d_in[8];
    const float* Wl1  = (const float*)d_in[9];
    const float* bl1  = (const float*)d_in[10];
    const float* Wl2  = (const float*)d_in[11];
    const float* bl2  = (const float*)d_in[12];
    const float* Wa1  = (const float*)d_in[13];
    const float* ba1  = (const float*)d_in[14];
    const float* Wa2  = (const float*)d_in[15];
    const float* ba2  = (const float*)d_in[16];

    float *eh, *et, *E1, *spill, *att, *red, *part;
    __nv_bfloat16 *P, *Xbf, *h1b, *hb, *ehs, *ets, *Ub, *Vb;
    __nv_bfloat16 *Wfc1b, *Wfc2b, *Whtb, *Wl1b, *Wl2b;
    int* tI;
    cudaGetSymbolAddress((void**)&P,     g_P);
    cudaGetSymbolAddress((void**)&eh,    g_eh);
    cudaGetSymbolAddress((void**)&et,    g_et);
    cudaGetSymbolAddress((void**)&E1,    g_E1);
    cudaGetSymbolAddress((void**)&spill, g_spill);
    cudaGetSymbolAddress((void**)&att,   g_att);
    cudaGetSymbolAddress((void**)&red,   g_red);
    cudaGetSymbolAddress((void**)&part,  g_part);
    cudaGetSymbolAddress((void**)&tI,    g_tI);
    cudaGetSymbolAddress((void**)&Xbf,   g_Xbf);
    cudaGetSymbolAddress((void**)&h1b,   g_h1b);
    cudaGetSymbolAddress((void**)&hb,    g_hb);
    cudaGetSymbolAddress((void**)&ehs,   g_ehs);
    cudaGetSymbolAddress((void**)&ets,   g_ets);
    cudaGetSymbolAddress((void**)&Ub,    g_Ub);
    cudaGetSymbolAddress((void**)&Vb,    g_Vb);
    cudaGetSymbolAddress((void**)&Wfc1b, g_Wfc1b);
    cudaGetSymbolAddress((void**)&Wfc2b, g_Wfc2b);
    cudaGetSymbolAddress((void**)&Whtb,  g_Whtb);
    cudaGetSymbolAddress((void**)&Wl1b,  g_Wl1b);
    cudaGetSymbolAddress((void**)&Wl2b,  g_Wl2b);

    const int smemNeed = 3 * MMA_STG;
    cudaFuncSetAttribute(attn_mma_kernel,
                         cudaFuncAttributeMaxDynamicSharedMemorySize, smemNeed);
    cudaFuncSetAttribute(ht_gemm_kernel,
                         cudaFuncAttributeMaxDynamicSharedMemorySize, smemNeed);
    cudaFuncSetAttribute(mma_gemm_kernel<1, true,  false>,
                         cudaFuncAttributeMaxDynamicSharedMemorySize, smemNeed);
    cudaFuncSetAttribute(mma_gemm_kernel<0, true,  false>,
                         cudaFuncAttributeMaxDynamicSharedMemorySize, smemNeed);
    cudaFuncSetAttribute(mma_gemm_kernel<0, true,  true>,
                         cudaFuncAttributeMaxDynamicSharedMemorySize, smemNeed);

    float* out = (float*)d_out;
    const size_t ND = (size_t)NN_ * DD_;
    float* e_out;
    float* eg_out;
    if ((size_t)out_size >= ND + DD_)      { e_out = out;   eg_out = out + ND; }
    else if ((size_t)out_size >= ND)       { e_out = out;   eg_out = nullptr;  }
    else                                   { e_out = spill; eg_out = out;      }

    const dim3 gG(2, 64);
    const dim3 gHT(4, 64);
    const dim3 gA(64, 64);

    xsplit_kernel<<<NN_, 256>>>(x, Xbf);
    wprep6_kernel<<<DIN_ + 5 * DD_, 256>>>(Wfc1, Wfc2, Whd, Wtl, Wl1, Wl2,
                                           Wfc1b, Wfc2b, Whtb, Whtb + 256 * KA3_,
                                           Wl1b, Wl2b);

    mma_gemm_kernel<1, true, false><<<gG, 512, smemNeed>>>(Xbf, Wfc1b, bfc1, nullptr, nullptr, h1b, KAX3_);
    mma_gemm_kernel<1, true, false><<<gG, 512, smemNeed>>>(h1b, Wfc2b, bfc2, nullptr, nullptr, hb,  KA3_);
    ht_gemm_kernel<<<gHT, 512, smemNeed>>>(hb, Whtb, bhd, btl, eh, et, ehs, ets);

    attn_mma_kernel<<<gA, 256, smemNeed>>>(ehs, ets, P);
    topk_kernel    <<<NN_, 256>>>(P, tI);
    neighbor_kernel<<<NN_, 256>>>(eh, et, tI, Ub, Vb);

    mma_gemm_kernel<0, true, false><<<gG, 512, smemNeed>>>(Ub, Wl1b, bl1, nullptr, E1,    nullptr, KA3_);
    mma_gemm_kernel<0, true, true ><<<gG, 512, smemNeed>>>(Vb, Wl2b, bl2, E1,      e_out, nullptr, KA3_);

    if (eg_out) {
        att_kernel   <<<NN_ / 16, 128>>>(e_out, Wa1, ba1, Wa2, ba2, att);
        smred_kernel <<<1, 1024>>>(att, red);
        egpart_kernel<<<32, 256>>>(att, e_out, red, part);
        egfin_kernel <<<1, 256>>>(part, red, eg_out);
    }
}

// round 16
// speedup vs baseline: 1.0545x; 1.0545x over previous
#include <cuda_runtime.h>
#include <cuda_bf16.h>
#include <math_constants.h>
#include <cstdint>

#define NN_  8192
#define DIN_ 1024
#define DD_  256
#define KT_  30
#define KS_  40     // screened candidates per row
#define KA3_ 768    // 3-term split of K=256
#define KAX3_ 3072  // 3-term split of K=1024

// ---------------- scratch ----------------------------------------------------
__device__ __nv_bfloat16 g_P[(size_t)NN_ * NN_];   // hi-only screening logits (128 MB)
__device__ float g_eh[NN_ * DD_];
__device__ float g_et[NN_ * DD_];
__device__ float g_E1[NN_ * DD_];
__device__ float g_spill[NN_ * DD_];
__device__ __nv_bfloat16 g_Xbf [(size_t)NN_ * KAX3_];
__device__ __nv_bfloat16 g_h1b [(size_t)NN_ * KA3_];
__device__ __nv_bfloat16 g_hb  [(size_t)NN_ * KA3_];
__device__ __nv_bfloat16 g_ehs [(size_t)NN_ * DD_];
__device__ __nv_bfloat16 g_ets [(size_t)NN_ * DD_];
__device__ __nv_bfloat16 g_Ub  [(size_t)NN_ * KA3_];
__device__ __nv_bfloat16 g_Vb  [(size_t)NN_ * KA3_];
__device__ __nv_bfloat16 g_Wfc1b[(size_t)DD_ * KAX3_];
__device__ __nv_bfloat16 g_Wfc2b[DD_ * KA3_];
__device__ __nv_bfloat16 g_Whtb [2 * DD_ * KA3_];
__device__ __nv_bfloat16 g_Wl1b [DD_ * KA3_];
__device__ __nv_bfloat16 g_Wl2b [DD_ * KA3_];
__device__ int   g_tI[NN_ * KS_];
__device__ float g_att[NN_];
__device__ float g_red[2];
__device__ float g_part[32 * DD_];

// =================== warp-MMA helpers ========================================
__device__ __forceinline__ uint32_t smem_u32(const void* p) {
    uint32_t a;
    asm("{ .reg .u64 t; cvta.to.shared.u64 t, %1; cvt.u32.u64 %0, t; }" : "=r"(a) : "l"(p));
    return a;
}
#define SW128(off) ((off) ^ (((off) >> 3) & 0x70))
#define CP16(dst, src)    asm volatile("cp.async.cg.shared.global [%0], [%1], 16;" :: "r"(dst), "l"(src) : "memory")
#define CP_COMMIT()       asm volatile("cp.async.commit_group;" ::: "memory")

__device__ __forceinline__ void ldsm4(uint32_t* r, uint32_t addr) {
    asm volatile("ldmatrix.sync.aligned.m8n8.x4.shared.b16 {%0,%1,%2,%3}, [%4];"
        : "=r"(r[0]), "=r"(r[1]), "=r"(r[2]), "=r"(r[3]) : "r"(addr));
}
__device__ __forceinline__ void mma16816(float* d, const uint32_t* a, const uint32_t* b) {
    asm volatile("mma.sync.aligned.m16n8k16.row.col.f32.bf16.bf16.f32 "
        "{%0,%1,%2,%3}, {%4,%5,%6,%7}, {%8,%9}, {%0,%1,%2,%3};"
        : "+f"(d[0]), "+f"(d[1]), "+f"(d[2]), "+f"(d[3])
        : "r"(a[0]), "r"(a[1]), "r"(a[2]), "r"(a[3]), "r"(b[0]), "r"(b[1]));
}

// ---------------- prep --------------------------------------------------------
__global__ void __launch_bounds__(256) xsplit_kernel(const float* __restrict__ x,
                                                     __nv_bfloat16* __restrict__ X)
{
    const int r = blockIdx.x;
    const int t = threadIdx.x;
    float4 v = reinterpret_cast<const float4*>(x + (size_t)r * DIN_)[t];
    __nv_bfloat16 h0 = __float2bfloat16(v.x), h1 = __float2bfloat16(v.y);
    __nv_bfloat16 h2 = __float2bfloat16(v.z), h3 = __float2bfloat16(v.w);
    __nv_bfloat16 l0 = __float2bfloat16(v.x - __bfloat162float(h0));
    __nv_bfloat16 l1 = __float2bfloat16(v.y - __bfloat162float(h1));
    __nv_bfloat16 l2 = __float2bfloat16(v.z - __bfloat162float(h2));
    __nv_bfloat16 l3 = __float2bfloat16(v.w - __bfloat162float(h3));
    __nv_bfloat16* row = X + (size_t)r * KAX3_ + 4 * t;
    __nv_bfloat162 H01; H01.x = h0; H01.y = h1;
    __nv_bfloat162 H23; H23.x = h2; H23.y = h3;
    __nv_bfloat162 L01; L01.x = l0; L01.y = l1;
    __nv_bfloat162 L23; L23.x = l2; L23.y = l3;
    reinterpret_cast<__nv_bfloat162*>(row)[0] = H01;
    reinterpret_cast<__nv_bfloat162*>(row)[1] = H23;
    reinterpret_cast<__nv_bfloat162*>(row + DIN_)[0] = L01;
    reinterpret_cast<__nv_bfloat162*>(row + DIN_)[1] = L23;
    reinterpret_cast<__nv_bfloat162*>(row + 2 * DIN_)[0] = H01;
    reinterpret_cast<__nv_bfloat162*>(row + 2 * DIN_)[1] = H23;
}
__global__ void __launch_bounds__(256) wprep6_kernel(
    const float* __restrict__ W1, const float* __restrict__ W2,
    const float* __restrict__ W3, const float* __restrict__ W4,
    const float* __restrict__ W5, const float* __restrict__ W6,
    __nv_bfloat16* __restrict__ B1, __nv_bfloat16* __restrict__ B2,
    __nv_bfloat16* __restrict__ B3, __nv_bfloat16* __restrict__ B4,
    __nv_bfloat16* __restrict__ B5, __nv_bfloat16* __restrict__ B6)
{
    int bid = blockIdx.x;
    const float* W; __nv_bfloat16* B; int K, k;
    if (bid < 1024)      { W = W1; B = B1; K = DIN_; k = bid; }
    else {
        bid -= 1024;
        const int s = bid >> 8;
        k = bid & 255; K = DD_;
        switch (s) {
            case 0: W = W2; B = B2; break;
            case 1: W = W3; B = B3; break;
            case 2: W = W4; B = B4; break;
            case 3: W = W5; B = B5; break;
            default: W = W6; B = B6; break;
        }
    }
    const int n = threadIdx.x;
    float v = W[(size_t)k * DD_ + n];
    __nv_bfloat16 h = __float2bfloat16(v);
    __nv_bfloat16 l = __float2bfloat16(v - __bfloat162float(h));
    __nv_bfloat16* row = B + (size_t)n * (3 * K);
    row[k] = h; row[K + k] = h; row[2*K + k] = l;
}

#define MMA_STG 32768

// ---------------- tile fill, 512-thread version ------------------------------
__device__ __forceinline__ void tile_fill(uint32_t sbase, int kc, int bm, int bn,
    const __nv_bfloat16* __restrict__ Ag, const __nv_bfloat16* __restrict__ Bg,
    int tid, int Ka)
{
    #pragma unroll
    for (int i = 0; i < 2; i++) {
        int q = tid + i * 512;
        int row = q >> 3, c = q & 7;
        const __nv_bfloat16* src = Ag + (size_t)(bm * 128 + row) * Ka + kc * 64 + c * 8;
        CP16(sbase + SW128((uint32_t)(row * 128 + c * 16)), src);
    }
    #pragma unroll
    for (int i = 0; i < 2; i++) {
        int q = tid + i * 512;
        int row = q >> 3, c = q & 7;
        const __nv_bfloat16* src = Bg + (size_t)(bn * 128 + row) * Ka + kc * 64 + c * 8;
        CP16(sbase + 16384 + SW128((uint32_t)(row * 128 + c * 16)), src);
    }
}
// ---------------- tile fill, 256-thread version ------------------------------
__device__ __forceinline__ void tile_fill8(uint32_t sbase, int kc, int bm, int bn,
    const __nv_bfloat16* __restrict__ Ag, const __nv_bfloat16* __restrict__ Bg,
    int tid, int Ka)
{
    #pragma unroll
    for (int i = 0; i < 4; i++) {
        int q = tid + i * 256;
        int row = q >> 3, c = q & 7;
        const __nv_bfloat16* src = Ag + (size_t)(bm * 128 + row) * Ka + kc * 64 + c * 8;
        CP16(sbase + SW128((uint32_t)(row * 128 + c * 16)), src);
    }
    #pragma unroll
    for (int i = 0; i < 4; i++) {
        int q = tid + i * 256;
        int row = q >> 3, c = q & 7;
        const __nv_bfloat16* src = Bg + (size_t)(bn * 128 + row) * Ka + kc * 64 + c * 8;
        CP16(sbase + 16384 + SW128((uint32_t)(row * 128 + c * 16)), src);
    }
}

// ---------------- 16-warp mainloop (trunk GEMMs) -----------------------------
struct MmaAcc { float a[2][4][4]; };

__device__ __forceinline__ void mma_mainloop(MmaAcc& A_, uint32_t sb, int nchunk,
    int bm, int bn, const __nv_bfloat16* Ag, const __nv_bfloat16* Bg, int Ka,
    int tid, int wid, int lane)
{
    const int wm = (wid & 3) * 32;
    const int wn = (wid >> 2) * 32;
    const int aRow = (lane & 15);
    const int aKb  = (lane >> 4) * 16;
    const int bRow = ((lane >> 4) << 3) + (lane & 7);
    const int bKb  = ((lane >> 3) & 1) * 16;

    uint32_t aOff[2], bOff[2];
    aOff[0] = SW128((uint32_t)((wm +      aRow) * 128 + aKb));
    aOff[1] = SW128((uint32_t)((wm + 16 + aRow) * 128 + aKb));
    bOff[0] = SW128((uint32_t)((wn +      bRow) * 128 + bKb)) + 16384u;
    bOff[1] = SW128((uint32_t)((wn + 16 + bRow) * 128 + bKb)) + 16384u;

    tile_fill(sb,           0, bm, bn, Ag, Bg, tid, Ka);
    CP_COMMIT();
    tile_fill(sb + MMA_STG, 1, bm, bn, Ag, Bg, tid, Ka);
    CP_COMMIT();

    int sidx = 0;
    for (int c = 0; c < nchunk; c++) {
        asm volatile("cp.async.wait_group 1;" ::: "memory");
        __syncthreads();

        if (c + 2 < nchunk) {
            int s2 = sidx + 2; if (s2 >= 3) s2 -= 3;
            tile_fill(sb + s2 * MMA_STG, c + 2, bm, bn, Ag, Bg, tid, Ka);
            CP_COMMIT();
        }

        const uint32_t stg = sb + sidx * MMA_STG;
        uint32_t abuf[2][2][4], bbuf[2][2][4];
        ldsm4(abuf[0][0], stg + aOff[0]);
        ldsm4(abuf[0][1], stg + aOff[1]);
        ldsm4(bbuf[0][0], stg + bOff[0]);
        ldsm4(bbuf[0][1], stg + bOff[1]);
        #pragma unroll
        for (int ks = 0; ks < 4; ks++) {
            const int cur = ks & 1, nxt = cur ^ 1;
            if (ks < 3) {
                const uint32_t x = (uint32_t)(ks + 1) << 5;
                ldsm4(abuf[nxt][0], (stg + aOff[0]) ^ x);
                ldsm4(abuf[nxt][1], (stg + aOff[1]) ^ x);
                ldsm4(bbuf[nxt][0], (stg + bOff[0]) ^ x);
                ldsm4(bbuf[nxt][1], (stg + bOff[1]) ^ x);
            }
            #pragma unroll
            for (int mt = 0; mt < 2; mt++)
                #pragma unroll
                for (int n8 = 0; n8 < 4; n8++)
                    mma16816(A_.a[mt][n8], abuf[cur][mt], &bbuf[cur][n8 >> 1][(n8 & 1) * 2]);
        }
        if (++sidx == 3) sidx = 0;
    }
}

// ---------------- 8-warp mainloop (attn GEMM, 2 CTA/SM) ----------------------
struct MmaAcc8 { float a[2][8][4]; };

__device__ __forceinline__ void mma_mainloop8(MmaAcc8& A_, uint32_t sb, int nchunk,
    int bm, int bn, const __nv_bfloat16* Ag, const __nv_bfloat16* Bg, int Ka,
    int tid, int wid, int lane)
{
    const int wm = (wid & 3) * 32;
    const int wn = (wid >> 2) * 64;
    const int aRow = (lane & 15);
    const int aKb  = (lane >> 4) * 16;
    const int bRow = ((lane >> 4) << 3) + (lane & 7);
    const int bKb  = ((lane >> 3) & 1) * 16;

    uint32_t aOff[2], bOff[4];
    aOff[0] = SW128((uint32_t)((wm +      aRow) * 128 + aKb));
    aOff[1] = SW128((uint32_t)((wm + 16 + aRow) * 128 + aKb));
    #pragma unroll
    for (int nt = 0; nt < 4; nt++)
        bOff[nt] = SW128((uint32_t)((wn + nt * 16 + bRow) * 128 + bKb)) + 16384u;

    tile_fill8(sb,           0, bm, bn, Ag, Bg, tid, Ka);
    CP_COMMIT();
    tile_fill8(sb + MMA_STG, 1, bm, bn, Ag, Bg, tid, Ka);
    CP_COMMIT();

    int sidx = 0;
    for (int c = 0; c < nchunk; c++) {
        asm volatile("cp.async.wait_group 1;" ::: "memory");
        __syncthreads();

        if (c + 2 < nchunk) {
            int s2 = sidx + 2; if (s2 >= 3) s2 -= 3;
            tile_fill8(sb + s2 * MMA_STG, c + 2, bm, bn, Ag, Bg, tid, Ka);
            CP_COMMIT();
        }

        const uint32_t stg = sb + sidx * MMA_STG;
        uint32_t abuf[2][2][4], bbuf[2][4][4];
        ldsm4(abuf[0][0], stg + aOff[0]);
        ldsm4(abuf[0][1], stg + aOff[1]);
        #pragma unroll
        for (int nt = 0; nt < 4; nt++) ldsm4(bbuf[0][nt], stg + bOff[nt]);
        #pragma unroll
        for (int ks = 0; ks < 4; ks++) {
            const int cur = ks & 1, nxt = cur ^ 1;
            if (ks < 3) {
                const uint32_t x = (uint32_t)(ks + 1) << 5;
                ldsm4(abuf[nxt][0], (stg + aOff[0]) ^ x);
                ldsm4(abuf[nxt][1], (stg + aOff[1]) ^ x);
                #pragma unroll
                for (int nt = 0; nt < 4; nt++)
                    ldsm4(bbuf[nxt][nt], (stg + bOff[nt]) ^ x);
            }
            #pragma unroll
            for (int mt = 0; mt < 2; mt++)
                #pragma unroll
                for (int n8 = 0; n8 < 8; n8++)
                    mma16816(A_.a[mt][n8], abuf[cur][mt], &bbuf[cur][n8 >> 1][(n8 & 1) * 2]);
        }
        if (++sidx == 3) sidx = 0;
    }
}

// ------- attn screening GEMM: P(bf16) = ehs @ ets^T (hi-only, K=256) ---------
__global__ void __launch_bounds__(256, 2) attn_mma_kernel(
    const __nv_bfloat16* __restrict__ Ag, const __nv_bfloat16* __restrict__ Bg,
    __nv_bfloat16* __restrict__ P)
{
    extern __shared__ char smem[];
    const uint32_t sb = smem_u32(smem);
    const int tid = threadIdx.x, wid = tid >> 5, lane = tid & 31;
    const int bn = blockIdx.x, bm = blockIdx.y;

    MmaAcc8 acc;
    #pragma unroll
    for (int i = 0; i < 2; i++)
        #pragma unroll
        for (int j = 0; j < 8; j++)
            #pragma unroll
            for (int q = 0; q < 4; q++) acc.a[i][j][q] = 0.f;

    mma_mainloop8(acc, sb, DD_ / 64, bm, bn, Ag, Bg, DD_, tid, wid, lane);

    const int wm = (wid & 3) * 32, wn = (wid >> 2) * 64;
    const int tig = lane & 3, gid = lane >> 2;
    #pragma unroll
    for (int mt = 0; mt < 2; mt++) {
        const int r0 = bm * 128 + wm + mt * 16 + gid;
        #pragma unroll
        for (int n8 = 0; n8 < 8; n8++) {
            const int cc = bn * 128 + wn + n8 * 8 + tig * 2;
            *reinterpret_cast<__nv_bfloat162*>(P + (size_t)r0 * NN_ + cc)
                = __floats2bfloat162_rn(acc.a[mt][n8][0], acc.a[mt][n8][1]);
            *reinterpret_cast<__nv_bfloat162*>(P + (size_t)(r0 + 8) * NN_ + cc)
                = __floats2bfloat162_rn(acc.a[mt][n8][2], acc.a[mt][n8][3]);
        }
    }
}

// ---------------- trunk GEMM with fused split epilogues ----------------------
template<int OSPL, bool RELU, bool HASADD>
__global__ void __launch_bounds__(512, 1) mma_gemm_kernel(
    const __nv_bfloat16* __restrict__ Ag, const __nv_bfloat16* __restrict__ Bg,
    const float* __restrict__ bias, const float* __restrict__ addend,
    float* __restrict__ C, __nv_bfloat16* __restrict__ S, int Ka)
{
    extern __shared__ char smem[];
    const uint32_t sb = smem_u32(smem);
    const int tid = threadIdx.x, wid = tid >> 5, lane = tid & 31;
    const int bn = blockIdx.x, bm = blockIdx.y;

    MmaAcc acc;
    #pragma unroll
    for (int i = 0; i < 2; i++)
        #pragma unroll
        for (int j = 0; j < 4; j++)
            #pragma unroll
            for (int q = 0; q < 4; q++) acc.a[i][j][q] = 0.f;

    mma_mainloop(acc, sb, Ka / 64, bm, bn, Ag, Bg, Ka, tid, wid, lane);

    const int wm = (wid & 3) * 32, wn = (wid >> 2) * 32;
    const int tig = lane & 3, gid = lane >> 2;
    #pragma unroll
    for (int mt = 0; mt < 2; mt++) {
        #pragma unroll
        for (int n8 = 0; n8 < 4; n8++) {
            const int cc = bn * 128 + wn + n8 * 8 + tig * 2;
            #pragma unroll
            for (int hh = 0; hh < 2; hh++) {
                const int r = bm * 128 + wm + mt * 16 + gid + hh * 8;
                #pragma unroll
                for (int e = 0; e < 2; e++) {
                    const int c = cc + e;
                    float v = acc.a[mt][n8][hh * 2 + e] + bias[c];
                    if (RELU)   v = fmaxf(v, 0.f);
                    if (HASADD) v += addend[(size_t)r * DD_ + c];
                    if (C) C[(size_t)r * DD_ + c] = v;
                    if (OSPL == 1) {
                        __nv_bfloat16 h = __float2bfloat16(v);
                        __nv_bfloat16 l = __float2bfloat16(v - __bfloat162float(h));
                        __nv_bfloat16* row = S + (size_t)r * KA3_;
                        row[c] = h; row[DD_ + c] = l; row[2*DD_ + c] = h;
                    }
                }
            }
        }
    }
}

// -------- fused head+tail GEMM: N=512, cols<256 -> eh/ehs, >=256 -> et/ets ----
__global__ void __launch_bounds__(512, 1) ht_gemm_kernel(
    const __nv_bfloat16* __restrict__ Ag, const __nv_bfloat16* __restrict__ Bg,
    const float* __restrict__ bhd, const float* __restrict__ btl,
    float* __restrict__ eh, float* __restrict__ et,
    __nv_bfloat16* __restrict__ ehs, __nv_bfloat16* __restrict__ ets)
{
    extern __shared__ char smem[];
    const uint32_t sb = smem_u32(smem);
    const int tid = threadIdx.x, wid = tid >> 5, lane = tid & 31;
    const int bn = blockIdx.x, bm = blockIdx.y;

    MmaAcc acc;
    #pragma unroll
    for (int i = 0; i < 2; i++)
        #pragma unroll
        for (int j = 0; j < 4; j++)
            #pragma unroll
            for (int q = 0; q < 4; q++) acc.a[i][j][q] = 0.f;

    mma_mainloop(acc, sb, KA3_ / 64, bm, bn, Ag, Bg, KA3_, tid, wid, lane);

    const int wm = (wid & 3) * 32, wn = (wid >> 2) * 32;
    const int tig = lane & 3, gid = lane >> 2;
    #pragma unroll
    for (int mt = 0; mt < 2; mt++) {
        #pragma unroll
        for (int n8 = 0; n8 < 4; n8++) {
            const int cc = bn * 128 + wn + n8 * 8 + tig * 2;
            #pragma unroll
            for (int hh = 0; hh < 2; hh++) {
                const int r = bm * 128 + wm + mt * 16 + gid + hh * 8;
                #pragma unroll
                for (int e = 0; e < 2; e++) {
                    const int c = cc + e;
                    if (c < 256) {
                        float v = acc.a[mt][n8][hh * 2 + e] + bhd[c];
                        eh [(size_t)r * DD_ + c] = v;
                        ehs[(size_t)r * DD_ + c] = __float2bfloat16(v * 0.0625f);
                    } else {
                        const int c2 = c - 256;
                        float v = acc.a[mt][n8][hh * 2 + e] + btl[c2];
                        et [(size_t)r * DD_ + c2] = v;
                        ets[(size_t)r * DD_ + c2] = __float2bfloat16(v);
                    }
                }
            }
        }
    }
}

// ---------------- per-row top-40 screening via 12-bit radix ------------------
// slot s = 8*j + e  ->  global idx = 8*(tid + j*256) + e
#define TK_CAP 512
__global__ void __launch_bounds__(256) topk_kernel(const __nv_bfloat16* __restrict__ P,
                                                   int* __restrict__ tI)
{
    const int row  = blockIdx.x;
    const int tid  = threadIdx.x;
    const int lane = tid & 31, w = tid >> 5;
    const uint4* p4 = reinterpret_cast<const uint4*>(P + (size_t)row * NN_);

    float v[32];
    uint32_t key[32];
    #pragma unroll
    for (int j = 0; j < 4; j++) {
        uint4 pk = p4[tid + j * 256];
        uint32_t ws[4] = {pk.x, pk.y, pk.z, pk.w};
        #pragma unroll
        for (int h = 0; h < 4; h++) {
            __nv_bfloat162 b2 = *reinterpret_cast<const __nv_bfloat162*>(&ws[h]);
            float2 f = __bfloat1622float2(b2);
            const int s = 8 * j + 2 * h;
            v[s]   = f.x;
            v[s+1] = f.y;
            uint32_t u0 = __float_as_uint(f.x);
            uint32_t u1 = __float_as_uint(f.y);
            key[s]   = (u0 & 0x80000000u) ? ~u0 : (u0 | 0x80000000u);
            key[s+1] = (u1 & 0x80000000u) ? ~u1 : (u1 | 0x80000000u);
        }
    }

    __shared__ int   hist[4096];
    __shared__ int   part[256];
    __shared__ int   sPivot[4];
    __shared__ float sV[KS_];
    __shared__ int   sI[KS_];
    __shared__ float cV[TK_CAP];
    __shared__ int   cI[TK_CAP];
    __shared__ int   cnts[2];

    #pragma unroll
    for (int i = 0; i < 16; i++) hist[tid * 16 + i] = 0;
    if (tid < 2) cnts[tid] = 0;
    __syncthreads();

    #pragma unroll
    for (int s = 0; s < 32; s++) atomicAdd(&hist[key[s] >> 20], 1);
    __syncthreads();

    {
        int s = 0;
        #pragma unroll
        for (int i = 0; i < 16; i++) s += hist[tid * 16 + i];
        part[tid] = s;
    }
    __syncthreads();
    if (tid == 0) {
        int acc = 0, t = 255;
        for (; t >= 0; t--) { acc += part[t]; if (acc >= KS_) break; }
        int cntAbove = acc - part[t];
        int b = -1;
        for (int bin = t * 16 + 15; bin >= t * 16; bin--) {
            int h = hist[bin];
            if (cntAbove + h >= KS_) { b = bin; break; }
            cntAbove += h;
        }
        sPivot[0] = b; sPivot[1] = cntAbove;
        sPivot[2] = 0;
    }
    __syncthreads();

    const uint32_t pb = (uint32_t)sPivot[0];
    const int nAbove  = sPivot[1];

    #pragma unroll
    for (int s = 0; s < 32; s++) {
        uint32_t bin = key[s] >> 20;
        if (bin > pb) {
            int pos = atomicAdd(&cnts[0], 1);
            sV[pos] = v[s]; sI[pos] = 8 * (tid + (s >> 3) * 256) + (s & 7);
        } else if (bin == pb) {
            int pos = atomicAdd(&cnts[1], 1);
            if (pos < TK_CAP) { cV[pos] = v[s]; cI[pos] = 8 * (tid + (s >> 3) * 256) + (s & 7); }
            else sPivot[2] = 1;
        }
    }
    __syncthreads();

    if (sPivot[2] == 0) {
        if (tid < 32) {
            const int ncand = min(cnts[1], TK_CAP);
            const int need  = KS_ - nAbove;
            float mv[16]; int mi[16];
            #pragma unroll
            for (int q = 0; q < 16; q++) {
                int idx = tid + q * 32;
                if (idx < ncand) { mv[q] = cV[idx]; mi[q] = cI[idx]; }
                else             { mv[q] = -CUDART_INF_F; mi[q] = 0x7fffffff; }
            }
            for (int it = 0; it < need; it++) {
                float bv = mv[0]; int bi = mi[0], bq = 0;
                #pragma unroll
                for (int q = 1; q < 16; q++)
                    if (mv[q] > bv || (mv[q] == bv && mi[q] < bi)) { bv = mv[q]; bi = mi[q]; bq = q; }
                float wv = bv; int wi = bi;
                #pragma unroll
                for (int off = 16; off; off >>= 1) {
                    float ov = __shfl_xor_sync(0xffffffffu, wv, off);
                    int   oi = __shfl_xor_sync(0xffffffffu, wi, off);
                    if (ov > wv || (ov == wv && oi < wi)) { wv = ov; wi = oi; }
                }
                if (bi == wi && bv == wv && bi != 0x7fffffff) {
                    sI[nAbove + it] = wi;
                    mv[bq] = -CUDART_INF_F; mi[bq] = 0x7fffffff;
                }
                __syncwarp();
            }
        }
        __syncthreads();
    } else {
        // degenerate fallback: exact iterative argmax
        __syncthreads();
        __shared__ float fV[8]; __shared__ int fI[9];
        float bv = v[0]; int bs = 0;
        #pragma unroll
        for (int s = 1; s < 32; s++) if (v[s] > bv) { bv = v[s]; bs = s; }
        for (int it = 0; it < KS_; it++) {
            float wv = bv; int wi = 8 * (tid + (bs >> 3) * 256) + (bs & 7);
            #pragma unroll
            for (int off = 16; off; off >>= 1) {
                float ov = __shfl_xor_sync(0xffffffffu, wv, off);
                int   oi = __shfl_xor_sync(0xffffffffu, wi, off);
                if (ov > wv || (ov == wv && oi < wi)) { wv = ov; wi = oi; }
            }
            if (lane == 0) { fV[w] = wv; fI[w] = wi; }
            __syncthreads();
            if (tid == 0) {
                float Bv = fV[0]; int Bi = fI[0];
                #pragma unroll
                for (int q = 1; q < 8; q++)
                    if (fV[q] > Bv || (fV[q] == Bv && fI[q] < Bi)) { Bv = fV[q]; Bi = fI[q]; }
                sI[it] = Bi; fI[8] = Bi;
            }
            __syncthreads();
            const int win = fI[8];
            if (((win >> 3) & 255) == tid) {
                v[8 * (win >> 11) + (win & 7)] = -CUDART_INF_F;
                bv = v[0]; bs = 0;
                #pragma unroll
                for (int s = 1; s < 32; s++) if (v[s] > bv) { bv = v[s]; bs = s; }
            }
        }
        __syncthreads();
    }

    if (tid < KS_) tI[row * KS_ + tid] = sI[tid];
}

// ------ fused rescore + parallel-rank exact top-30 + neighbor aggregation ----
__global__ void __launch_bounds__(256) neighbor_kernel(
    const float* __restrict__ eH, const float* __restrict__ eT,
    const int* __restrict__ tI,
    __nv_bfloat16* __restrict__ Ub, __nv_bfloat16* __restrict__ Vb)
{
    const int row  = blockIdx.x;
    const int d    = threadIdx.x;
    const int lane = d & 31, w = d >> 5;

    __shared__ __align__(16) float sNb[KS_][DD_];
    __shared__ __align__(16) float sEh[DD_];
    __shared__ float sVal[KS_];
    __shared__ int   sIdx[KS_];
    __shared__ int   sSel[KT_];
    __shared__ float sSelV[KT_];
    __shared__ float sPr[KT_];
    __shared__ float sW[KT_];
    __shared__ float sKa[KT_];

    const float eh = eH[(size_t)row * DD_ + d];
    sEh[d] = eh;
    if (d < KS_) sIdx[d] = tI[row * KS_ + d];
    __syncthreads();

    // batched gather: each warp owns rows w, w+8, ..., w+32 (all 10 LDG.128 in flight)
    float4 t0[5], t1[5];
    #pragma unroll
    for (int i = 0; i < 5; i++) {
        const int k = w + i * 8;
        const float4* src = reinterpret_cast<const float4*>(eT + (size_t)sIdx[k] * DD_);
        t0[i] = src[lane];
        t1[i] = src[lane + 32];
    }
    {
        const float4* eh4 = reinterpret_cast<const float4*>(sEh);
        #pragma unroll
        for (int i = 0; i < 5; i++) {
            const int k = w + i * 8;
            float4* dst = reinterpret_cast<float4*>(sNb[k]);
            dst[lane] = t0[i];
            dst[lane + 32] = t1[i];
            float dot = 0.f;
            {
                float4 t = t0[i]; float4 e4 = eh4[lane];
                dot += t.x * e4.x + t.y * e4.y + t.z * e4.z + t.w * e4.w;
            }
            {
                float4 t = t1[i]; float4 e4 = eh4[lane + 32];
                dot += t.x * e4.x + t.y * e4.y + t.z * e4.z + t.w * e4.w;
            }
            #pragma unroll
            for (int off = 16; off; off >>= 1) dot += __shfl_xor_sync(0xffffffffu, dot, off);
            if (lane == 0) sVal[k] = dot * 0.0625f;
        }
    }
    __syncthreads();

    // parallel rank select: exact top-30-of-40 by (value desc, idx asc)
    if (d < KS_) {
        const float vd = sVal[d];
        const int   id = sIdx[d];
        int rank = 0;
        #pragma unroll
        for (int j = 0; j < KS_; j++) {
            const float vj = sVal[j];
            const int   ij = sIdx[j];
            if (vj > vd || (vj == vd && ij < id)) rank++;
        }
        if (rank < KT_) { sSel[rank] = d; sSelV[rank] = vd; }
    }
    __syncthreads();

    if (d < 32) {
        float ev = (d < KT_) ? expf(sSelV[d] - sSelV[0]) : 0.f;
        float s = ev;
        #pragma unroll
        for (int off = 16; off; off >>= 1) s += __shfl_xor_sync(0xffffffffu, s, off);
        if (d < KT_) sPr[d] = ev / s;
    }
    __syncthreads();

    for (int k = w; k < KT_; k += 8) {
        const int s = sSel[k];
        const float pk = sPr[k], ck = 2.f - pk;
        float snb = 0.f, sg = 0.f;
        #pragma unroll
        for (int q = 0; q < 8; q++) {
            const int dd = lane + q * 32;
            const float nb = sNb[s][dd];
            snb += nb;
            sg  += tanhf(ck * sEh[dd] + pk * nb);
        }
        #pragma unroll
        for (int off = 16; off; off >>= 1) {
            snb += __shfl_xor_sync(0xffffffffu, snb, off);
            sg  += __shfl_xor_sync(0xffffffffu, sg,  off);
        }
        if (lane == 0) sW[k] = snb * sg;
    }
    __syncthreads();

    if (d < 32) {
        float val = (d < KT_) ? sW[d] : -CUDART_INF_F;
        float m = val;
        #pragma unroll
        for (int off = 16; off; off >>= 1) m = fmaxf(m, __shfl_xor_sync(0xffffffffu, m, off));
        float ev = (d < KT_) ? expf(val - m) : 0.f;
        float s = ev;
        #pragma unroll
        for (int off = 16; off; off >>= 1) s += __shfl_xor_sync(0xffffffffu, s, off);
        if (d < KT_) sKa[d] = ev / s;
    }
    __syncthreads();

    float acc = 0.f;
    #pragma unroll
    for (int k = 0; k < KT_; k++) acc += sKa[k] * sNb[sSel[k]][d];

    const float u = eh + acc, vv = eh * acc;
    {
        __nv_bfloat16 h = __float2bfloat16(u);
        __nv_bfloat16 l = __float2bfloat16(u - __bfloat162float(h));
        __nv_bfloat16* rw = Ub + (size_t)row * KA3_;
        rw[d] = h; rw[DD_ + d] = l; rw[2*DD_ + d] = h;
    }
    {
        __nv_bfloat16 h = __float2bfloat16(vv);
        __nv_bfloat16 l = __float2bfloat16(vv - __bfloat162float(h));
        __nv_bfloat16* rw = Vb + (size_t)row * KA3_;
        rw[d] = h; rw[DD_ + d] = l; rw[2*DD_ + d] = h;
    }
}

// ---------------- attention head ----------------------------------------------
__global__ void __launch_bounds__(128) att_kernel(
    const float* __restrict__ E, const float* __restrict__ W1,
    const float* __restrict__ b1, const float* __restrict__ W2,
    const float* __restrict__ b2, float* __restrict__ att)
{
    const int r0 = blockIdx.x * 16;
    const int j  = threadIdx.x;
    __shared__ float sE[16][DD_];
    for (int t = j; t < 16 * DD_; t += 128)
        sE[t >> 8][t & 255] = E[(size_t)(r0 + (t >> 8)) * DD_ + (t & 255)];
    __syncthreads();

    float acc[16];
    #pragma unroll
    for (int r = 0; r < 16; r++) acc[r] = 0.f;
    for (int dd = 0; dd < DD_; dd++) {
        const float wv = W1[dd * 128 + j];
        #pragma unroll
        for (int r = 0; r < 16; r++) acc[r] += sE[r][dd] * wv;
    }
    const float bb = b1[j], w2 = W2[j];
    __shared__ float sRed[16][4];
    const int lane = j & 31, w = j >> 5;
    #pragma unroll
    for (int r = 0; r < 16; r++) {
        float val = acc[r] + bb;
        val = (val > 0.f) ? val : 0.01f * val;
        val *= w2;
        #pragma unroll
        for (int off = 16; off; off >>= 1) val += __shfl_xor_sync(0xffffffffu, val, off);
        if (lane == 0) sRed[r][w] = val;
    }
    __syncthreads();
    if (j < 16) att[r0 + j] = sRed[j][0] + sRed[j][1] + sRed[j][2] + sRed[j][3] + b2[0];
}

// ---------------- softmax-over-nodes reduction --------------------------------
__global__ void __launch_bounds__(1024) smred_kernel(const float* __restrict__ att,
                                                     float* __restrict__ red)
{
    const int tid = threadIdx.x;
    __shared__ float s[32];
    float m = -CUDART_INF_F;
    for (int i = tid; i < NN_; i += 1024) m = fmaxf(m, att[i]);
    #pragma unroll
    for (int off = 16; off; off >>= 1) m = fmaxf(m, __shfl_xor_sync(0xffffffffu, m, off));
    if ((tid & 31) == 0) s[tid >> 5] = m;
    __syncthreads();
    if (tid < 32) {
        float mm = s[tid];
        #pragma unroll
        for (int off = 16; off; off >>= 1) mm = fmaxf(mm, __shfl_xor_sync(0xffffffffu, mm, off));
        if (tid == 0) s[0] = mm;
    }
    __syncthreads();
    const float M = s[0];
    __syncthreads();
    float z = 0.f;
    for (int i = tid; i < NN_; i += 1024) z += expf(att[i] - M);
    #pragma unroll
    for (int off = 16; off; off >>= 1) z += __shfl_xor_sync(0xffffffffu, z, off);
    if ((tid & 31) == 0) s[tid >> 5] = z;
    __syncthreads();
    if (tid < 32) {
        float zz = s[tid];
        #pragma unroll
        for (int off = 16; off; off >>= 1) zz += __shfl_xor_sync(0xffffffffu, zz, off);
        if (tid == 0) { red[0] = M; red[1] = zz; }
    }
}

__global__ void __launch_bounds__(256) egpart_kernel(const float* __restrict__ att,
    const float* __restrict__ E, const float* __restrict__ red, float* __restrict__ part)
{
    const int b = blockIdx.x;
    const int d = threadIdx.x;
    __shared__ float wsh[256];
    wsh[d] = expf(att[b * 256 + d] - red[0]);
    __syncthreads();
    float acc = 0.f;
    const float* Eb = E + (size_t)b * 256 * DD_;
    for (int i = 0; i < 256; i++) acc += wsh[i] * Eb[(size_t)i * DD_ + d];
    part[b * DD_ + d] = acc;
}

__global__ void __launch_bounds__(256) egfin_kernel(const float* __restrict__ part,
    const float* __restrict__ red, float* __restrict__ eg)
{
    const int d = threadIdx.x;
    float s = 0.f;
    #pragma unroll
    for (int b = 0; b < 32; b++) s += part[b * DD_ + d];
    eg[d] = s / red[1];
}

// ---------------- launcher -----------------------------------------------------
extern "C" void kernel_launch(void* const* d_in, const int* in_sizes, int n_in,
                              void* d_out, int out_size)
{
    const float* x    = (const float*)d_in[0];
    const float* Wfc1 = (const float*)d_in[1];
    const float* bfc1 = (const float*)d_in[2];
    const float* Wfc2 = (const float*)d_in[3];
    const float* bfc2 = (const float*)d_in[4];
    const float* Whd  = (const float*)d_in[5];
    const float* bhd  = (const float*)d_in[6];
    const float* Wtl  = (const float*)d_in[7];
    const float* btl  = (const float*)d_in[8];
    const float* Wl1  = (const float*)d_in[9];
    const float* bl1  = (const float*)d_in[10];
    const float* Wl2  = (const float*)d_in[11];
    const float* bl2  = (const float*)d_in[12];
    const float* Wa1  = (const float*)d_in[13];
    const float* ba1  = (const float*)d_in[14];
    const float* Wa2  = (const float*)d_in[15];
    const float* ba2  = (const float*)d_in[16];

    float *eh, *et, *E1, *spill, *att, *red, *part;
    __nv_bfloat16 *P, *Xbf, *h1b, *hb, *ehs, *ets, *Ub, *Vb;
    __nv_bfloat16 *Wfc1b, *Wfc2b, *Whtb, *Wl1b, *Wl2b;
    int* tI;
    cudaGetSymbolAddress((void**)&P,     g_P);
    cudaGetSymbolAddress((void**)&eh,    g_eh);
    cudaGetSymbolAddress((void**)&et,    g_et);
    cudaGetSymbolAddress((void**)&E1,    g_E1);
    cudaGetSymbolAddress((void**)&spill, g_spill);
    cudaGetSymbolAddress((void**)&att,   g_att);
    cudaGetSymbolAddress((void**)&red,   g_red);
    cudaGetSymbolAddress((void**)&part,  g_part);
    cudaGetSymbolAddress((void**)&tI,    g_tI);
    cudaGetSymbolAddress((void**)&Xbf,   g_Xbf);
    cudaGetSymbolAddress((void**)&h1b,   g_h1b);
    cudaGetSymbolAddress((void**)&hb,    g_hb);
    cudaGetSymbolAddress((void**)&ehs,   g_ehs);
    cudaGetSymbolAddress((void**)&ets,   g_ets);
    cudaGetSymbolAddress((void**)&Ub,    g_Ub);
    cudaGetSymbolAddress((void**)&Vb,    g_Vb);
    cudaGetSymbolAddress((void**)&Wfc1b, g_Wfc1b);
    cudaGetSymbolAddress((void**)&Wfc2b, g_Wfc2b);
    cudaGetSymbolAddress((void**)&Whtb,  g_Whtb);
    cudaGetSymbolAddress((void**)&Wl1b,  g_Wl1b);
    cudaGetSymbolAddress((void**)&Wl2b,  g_Wl2b);

    const int smemNeed = 3 * MMA_STG;
    cudaFuncSetAttribute(attn_mma_kernel,
                         cudaFuncAttributeMaxDynamicSharedMemorySize, smemNeed);
    cudaFuncSetAttribute(ht_gemm_kernel,
                         cudaFuncAttributeMaxDynamicSharedMemorySize, smemNeed);
    cudaFuncSetAttribute(mma_gemm_kernel<1, true,  false>,
                         cudaFuncAttributeMaxDynamicSharedMemorySize, smemNeed);
    cudaFuncSetAttribute(mma_gemm_kernel<0, true,  false>,
                         cudaFuncAttributeMaxDynamicSharedMemorySize, smemNeed);
    cudaFuncSetAttribute(mma_gemm_kernel<0, true,  true>,
                         cudaFuncAttributeMaxDynamicSharedMemorySize, smemNeed);

    float* out = (float*)d_out;
    const size_t ND = (size_t)NN_ * DD_;
    float* e_out;
    float* eg_out;
    if ((size_t)out_size >= ND + DD_)      { e_out = out;   eg_out = out + ND; }
    else if ((size_t)out_size >= ND)       { e_out = out;   eg_out = nullptr;  }
    else                                   { e_out = spill; eg_out = out;      }

    const dim3 gG(2, 64);
    const dim3 gHT(4, 64);
    const dim3 gA(64, 64);

    xsplit_kernel<<<NN_, 256>>>(x, Xbf);
    wprep6_kernel<<<DIN_ + 5 * DD_, 256>>>(Wfc1, Wfc2, Whd, Wtl, Wl1, Wl2,
                                           Wfc1b, Wfc2b, Whtb, Whtb + 256 * KA3_,
                                           Wl1b, Wl2b);

    mma_gemm_kernel<1, true, false><<<gG, 512, smemNeed>>>(Xbf, Wfc1b, bfc1, nullptr, nullptr, h1b, KAX3_);
    mma_gemm_kernel<1, true, false><<<gG, 512, smemNeed>>>(h1b, Wfc2b, bfc2, nullptr, nullptr, hb,  KA3_);
    ht_gemm_kernel<<<gHT, 512, smemNeed>>>(hb, Whtb, bhd, btl, eh, et, ehs, ets);

    attn_mma_kernel<<<gA, 256, smemNeed>>>(ehs, ets, P);
    topk_kernel    <<<NN_, 256>>>(P, tI);
    neighbor_kernel<<<NN_, 256>>>(eh, et, tI, Ub, Vb);

    mma_gemm_kernel<0, true, false><<<gG, 512, smemNeed>>>(Ub, Wl1b, bl1, nullptr, E1,    nullptr, KA3_);
    mma_gemm_kernel<0, true, true ><<<gG, 512, smemNeed>>>(Vb, Wl2b, bl2, E1,      e_out, nullptr, KA3_);

    if (eg_out) {
        att_kernel   <<<NN_ / 16, 128>>>(e_out, Wa1, ba1, Wa2, ba2, att);
        smred_kernel <<<1, 1024>>>(att, red);
        egpart_kernel<<<32, 256>>>(att, e_out, red, part);
        egfin_kernel <<<1, 256>>>(part, red, eg_out);
    }
}

// round 17
// speedup vs baseline: 1.0950x; 1.0384x over previous
#include <cuda_runtime.h>
#include <cuda_bf16.h>
#include <math_constants.h>
#include <cstdint>

#define NN_  8192
#define DIN_ 1024
#define DD_  256
#define KT_  30
#define KS_  40     // screened candidates per row
#define KA3_ 768    // 3-term split of K=256
#define KAX3_ 3072  // 3-term split of K=1024

// ---------------- scratch ----------------------------------------------------
__device__ __nv_bfloat16 g_P[(size_t)NN_ * NN_];   // hi-only screening logits (128 MB)
__device__ float g_eh[NN_ * DD_];
__device__ float g_et[NN_ * DD_];
__device__ float g_E1[NN_ * DD_];
__device__ float g_spill[NN_ * DD_];
__device__ __nv_bfloat16 g_Xbf [(size_t)NN_ * KAX3_];
__device__ __nv_bfloat16 g_h1b [(size_t)NN_ * KA3_];
__device__ __nv_bfloat16 g_hb  [(size_t)NN_ * KA3_];
__device__ __nv_bfloat16 g_ehs [(size_t)NN_ * DD_];
__device__ __nv_bfloat16 g_ets [(size_t)NN_ * DD_];
__device__ __nv_bfloat16 g_Ub  [(size_t)NN_ * KA3_];
__device__ __nv_bfloat16 g_Vb  [(size_t)NN_ * KA3_];
__device__ __nv_bfloat16 g_Wfc1b[(size_t)DD_ * KAX3_];
__device__ __nv_bfloat16 g_Wfc2b[DD_ * KA3_];
__device__ __nv_bfloat16 g_Whtb [2 * DD_ * KA3_];
__device__ __nv_bfloat16 g_Wl1b [DD_ * KA3_];
__device__ __nv_bfloat16 g_Wl2b [DD_ * KA3_];
__device__ int   g_tI[NN_ * KS_];
__device__ float g_att[NN_];
__device__ float g_red[2];
__device__ float g_part[32 * DD_];

// =================== warp-MMA helpers ========================================
__device__ __forceinline__ uint32_t smem_u32(const void* p) {
    uint32_t a;
    asm("{ .reg .u64 t; cvta.to.shared.u64 t, %1; cvt.u32.u64 %0, t; }" : "=r"(a) : "l"(p));
    return a;
}
#define SW128(off) ((off) ^ (((off) >> 3) & 0x70))
#define CP16(dst, src)    asm volatile("cp.async.cg.shared.global [%0], [%1], 16;" :: "r"(dst), "l"(src) : "memory")
#define CP_COMMIT()       asm volatile("cp.async.commit_group;" ::: "memory")

__device__ __forceinline__ void ldsm4(uint32_t* r, uint32_t addr) {
    asm volatile("ldmatrix.sync.aligned.m8n8.x4.shared.b16 {%0,%1,%2,%3}, [%4];"
        : "=r"(r[0]), "=r"(r[1]), "=r"(r[2]), "=r"(r[3]) : "r"(addr));
}
__device__ __forceinline__ void mma16816(float* d, const uint32_t* a, const uint32_t* b) {
    asm volatile("mma.sync.aligned.m16n8k16.row.col.f32.bf16.bf16.f32 "
        "{%0,%1,%2,%3}, {%4,%5,%6,%7}, {%8,%9}, {%0,%1,%2,%3};"
        : "+f"(d[0]), "+f"(d[1]), "+f"(d[2]), "+f"(d[3])
        : "r"(a[0]), "r"(a[1]), "r"(a[2]), "r"(a[3]), "r"(b[0]), "r"(b[1]));
}

// ---------------- prep --------------------------------------------------------
__global__ void __launch_bounds__(256) xsplit_kernel(const float* __restrict__ x,
                                                     __nv_bfloat16* __restrict__ X)
{
    const int r = blockIdx.x;
    const int t = threadIdx.x;
    float4 v = reinterpret_cast<const float4*>(x + (size_t)r * DIN_)[t];
    __nv_bfloat16 h0 = __float2bfloat16(v.x), h1 = __float2bfloat16(v.y);
    __nv_bfloat16 h2 = __float2bfloat16(v.z), h3 = __float2bfloat16(v.w);
    __nv_bfloat16 l0 = __float2bfloat16(v.x - __bfloat162float(h0));
    __nv_bfloat16 l1 = __float2bfloat16(v.y - __bfloat162float(h1));
    __nv_bfloat16 l2 = __float2bfloat16(v.z - __bfloat162float(h2));
    __nv_bfloat16 l3 = __float2bfloat16(v.w - __bfloat162float(h3));
    __nv_bfloat16* row = X + (size_t)r * KAX3_ + 4 * t;
    __nv_bfloat162 H01; H01.x = h0; H01.y = h1;
    __nv_bfloat162 H23; H23.x = h2; H23.y = h3;
    __nv_bfloat162 L01; L01.x = l0; L01.y = l1;
    __nv_bfloat162 L23; L23.x = l2; L23.y = l3;
    reinterpret_cast<__nv_bfloat162*>(row)[0] = H01;
    reinterpret_cast<__nv_bfloat162*>(row)[1] = H23;
    reinterpret_cast<__nv_bfloat162*>(row + DIN_)[0] = L01;
    reinterpret_cast<__nv_bfloat162*>(row + DIN_)[1] = L23;
    reinterpret_cast<__nv_bfloat162*>(row + 2 * DIN_)[0] = H01;
    reinterpret_cast<__nv_bfloat162*>(row + 2 * DIN_)[1] = H23;
}
__global__ void __launch_bounds__(256) wprep6_kernel(
    const float* __restrict__ W1, const float* __restrict__ W2,
    const float* __restrict__ W3, const float* __restrict__ W4,
    const float* __restrict__ W5, const float* __restrict__ W6,
    __nv_bfloat16* __restrict__ B1, __nv_bfloat16* __restrict__ B2,
    __nv_bfloat16* __restrict__ B3, __nv_bfloat16* __restrict__ B4,
    __nv_bfloat16* __restrict__ B5, __nv_bfloat16* __restrict__ B6)
{
    int bid = blockIdx.x;
    const float* W; __nv_bfloat16* B; int K, k;
    if (bid < 1024)      { W = W1; B = B1; K = DIN_; k = bid; }
    else {
        bid -= 1024;
        const int s = bid >> 8;
        k = bid & 255; K = DD_;
        switch (s) {
            case 0: W = W2; B = B2; break;
            case 1: W = W3; B = B3; break;
            case 2: W = W4; B = B4; break;
            case 3: W = W5; B = B5; break;
            default: W = W6; B = B6; break;
        }
    }
    const int n = threadIdx.x;
    float v = W[(size_t)k * DD_ + n];
    __nv_bfloat16 h = __float2bfloat16(v);
    __nv_bfloat16 l = __float2bfloat16(v - __bfloat162float(h));
    __nv_bfloat16* row = B + (size_t)n * (3 * K);
    row[k] = h; row[K + k] = h; row[2*K + k] = l;
}

#define MMA_STG 32768

// ---------------- tile fill, 512-thread version ------------------------------
__device__ __forceinline__ void tile_fill(uint32_t sbase, int kc, int bm, int bn,
    const __nv_bfloat16* __restrict__ Ag, const __nv_bfloat16* __restrict__ Bg,
    int tid, int Ka)
{
    #pragma unroll
    for (int i = 0; i < 2; i++) {
        int q = tid + i * 512;
        int row = q >> 3, c = q & 7;
        const __nv_bfloat16* src = Ag + (size_t)(bm * 128 + row) * Ka + kc * 64 + c * 8;
        CP16(sbase + SW128((uint32_t)(row * 128 + c * 16)), src);
    }
    #pragma unroll
    for (int i = 0; i < 2; i++) {
        int q = tid + i * 512;
        int row = q >> 3, c = q & 7;
        const __nv_bfloat16* src = Bg + (size_t)(bn * 128 + row) * Ka + kc * 64 + c * 8;
        CP16(sbase + 16384 + SW128((uint32_t)(row * 128 + c * 16)), src);
    }
}
// ---------------- tile fill, 256-thread version ------------------------------
__device__ __forceinline__ void tile_fill8(uint32_t sbase, int kc, int bm, int bn,
    const __nv_bfloat16* __restrict__ Ag, const __nv_bfloat16* __restrict__ Bg,
    int tid, int Ka)
{
    #pragma unroll
    for (int i = 0; i < 4; i++) {
        int q = tid + i * 256;
        int row = q >> 3, c = q & 7;
        const __nv_bfloat16* src = Ag + (size_t)(bm * 128 + row) * Ka + kc * 64 + c * 8;
        CP16(sbase + SW128((uint32_t)(row * 128 + c * 16)), src);
    }
    #pragma unroll
    for (int i = 0; i < 4; i++) {
        int q = tid + i * 256;
        int row = q >> 3, c = q & 7;
        const __nv_bfloat16* src = Bg + (size_t)(bn * 128 + row) * Ka + kc * 64 + c * 8;
        CP16(sbase + 16384 + SW128((uint32_t)(row * 128 + c * 16)), src);
    }
}

// ---------------- 16-warp mainloop (trunk GEMMs) -----------------------------
struct MmaAcc { float a[2][4][4]; };

__device__ __forceinline__ void mma_mainloop(MmaAcc& A_, uint32_t sb, int nchunk,
    int bm, int bn, const __nv_bfloat16* Ag, const __nv_bfloat16* Bg, int Ka,
    int tid, int wid, int lane)
{
    const int wm = (wid & 3) * 32;
    const int wn = (wid >> 2) * 32;
    const int aRow = (lane & 15);
    const int aKb  = (lane >> 4) * 16;
    const int bRow = ((lane >> 4) << 3) + (lane & 7);
    const int bKb  = ((lane >> 3) & 1) * 16;

    uint32_t aOff[2], bOff[2];
    aOff[0] = SW128((uint32_t)((wm +      aRow) * 128 + aKb));
    aOff[1] = SW128((uint32_t)((wm + 16 + aRow) * 128 + aKb));
    bOff[0] = SW128((uint32_t)((wn +      bRow) * 128 + bKb)) + 16384u;
    bOff[1] = SW128((uint32_t)((wn + 16 + bRow) * 128 + bKb)) + 16384u;

    tile_fill(sb,           0, bm, bn, Ag, Bg, tid, Ka);
    CP_COMMIT();
    tile_fill(sb + MMA_STG, 1, bm, bn, Ag, Bg, tid, Ka);
    CP_COMMIT();

    int sidx = 0;
    for (int c = 0; c < nchunk; c++) {
        asm volatile("cp.async.wait_group 1;" ::: "memory");
        __syncthreads();

        if (c + 2 < nchunk) {
            int s2 = sidx + 2; if (s2 >= 3) s2 -= 3;
            tile_fill(sb + s2 * MMA_STG, c + 2, bm, bn, Ag, Bg, tid, Ka);
            CP_COMMIT();
        }

        const uint32_t stg = sb + sidx * MMA_STG;
        uint32_t abuf[2][2][4], bbuf[2][2][4];
        ldsm4(abuf[0][0], stg + aOff[0]);
        ldsm4(abuf[0][1], stg + aOff[1]);
        ldsm4(bbuf[0][0], stg + bOff[0]);
        ldsm4(bbuf[0][1], stg + bOff[1]);
        #pragma unroll
        for (int ks = 0; ks < 4; ks++) {
            const int cur = ks & 1, nxt = cur ^ 1;
            if (ks < 3) {
                const uint32_t x = (uint32_t)(ks + 1) << 5;
                ldsm4(abuf[nxt][0], (stg + aOff[0]) ^ x);
                ldsm4(abuf[nxt][1], (stg + aOff[1]) ^ x);
                ldsm4(bbuf[nxt][0], (stg + bOff[0]) ^ x);
                ldsm4(bbuf[nxt][1], (stg + bOff[1]) ^ x);
            }
            #pragma unroll
            for (int mt = 0; mt < 2; mt++)
                #pragma unroll
                for (int n8 = 0; n8 < 4; n8++)
                    mma16816(A_.a[mt][n8], abuf[cur][mt], &bbuf[cur][n8 >> 1][(n8 & 1) * 2]);
        }
        if (++sidx == 3) sidx = 0;
    }
}

// ---------------- 8-warp mainloop (attn GEMM, 2 CTA/SM) ----------------------
struct MmaAcc8 { float a[2][8][4]; };

__device__ __forceinline__ void mma_mainloop8(MmaAcc8& A_, uint32_t sb, int nchunk,
    int bm, int bn, const __nv_bfloat16* Ag, const __nv_bfloat16* Bg, int Ka,
    int tid, int wid, int lane)
{
    const int wm = (wid & 3) * 32;
    const int wn = (wid >> 2) * 64;
    const int aRow = (lane & 15);
    const int aKb  = (lane >> 4) * 16;
    const int bRow = ((lane >> 4) << 3) + (lane & 7);
    const int bKb  = ((lane >> 3) & 1) * 16;

    uint32_t aOff[2], bOff[4];
    aOff[0] = SW128((uint32_t)((wm +      aRow) * 128 + aKb));
    aOff[1] = SW128((uint32_t)((wm + 16 + aRow) * 128 + aKb));
    #pragma unroll
    for (int nt = 0; nt < 4; nt++)
        bOff[nt] = SW128((uint32_t)((wn + nt * 16 + bRow) * 128 + bKb)) + 16384u;

    tile_fill8(sb,           0, bm, bn, Ag, Bg, tid, Ka);
    CP_COMMIT();
    tile_fill8(sb + MMA_STG, 1, bm, bn, Ag, Bg, tid, Ka);
    CP_COMMIT();

    int sidx = 0;
    for (int c = 0; c < nchunk; c++) {
        asm volatile("cp.async.wait_group 1;" ::: "memory");
        __syncthreads();

        if (c + 2 < nchunk) {
            int s2 = sidx + 2; if (s2 >= 3) s2 -= 3;
            tile_fill8(sb + s2 * MMA_STG, c + 2, bm, bn, Ag, Bg, tid, Ka);
            CP_COMMIT();
        }

        const uint32_t stg = sb + sidx * MMA_STG;
        uint32_t abuf[2][2][4], bbuf[2][4][4];
        ldsm4(abuf[0][0], stg + aOff[0]);
        ldsm4(abuf[0][1], stg + aOff[1]);
        #pragma unroll
        for (int nt = 0; nt < 4; nt++) ldsm4(bbuf[0][nt], stg + bOff[nt]);
        #pragma unroll
        for (int ks = 0; ks < 4; ks++) {
            const int cur = ks & 1, nxt = cur ^ 1;
            if (ks < 3) {
                const uint32_t x = (uint32_t)(ks + 1) << 5;
                ldsm4(abuf[nxt][0], (stg + aOff[0]) ^ x);
                ldsm4(abuf[nxt][1], (stg + aOff[1]) ^ x);
                #pragma unroll
                for (int nt = 0; nt < 4; nt++)
                    ldsm4(bbuf[nxt][nt], (stg + bOff[nt]) ^ x);
            }
            #pragma unroll
            for (int mt = 0; mt < 2; mt++)
                #pragma unroll
                for (int n8 = 0; n8 < 8; n8++)
                    mma16816(A_.a[mt][n8], abuf[cur][mt], &bbuf[cur][n8 >> 1][(n8 & 1) * 2]);
        }
        if (++sidx == 3) sidx = 0;
    }
}

// ------- attn screening GEMM: P(bf16) = ehs @ ets^T (hi-only, K=256) ---------
__global__ void __launch_bounds__(256, 2) attn_mma_kernel(
    const __nv_bfloat16* __restrict__ Ag, const __nv_bfloat16* __restrict__ Bg,
    __nv_bfloat16* __restrict__ P)
{
    extern __shared__ char smem[];
    const uint32_t sb = smem_u32(smem);
    const int tid = threadIdx.x, wid = tid >> 5, lane = tid & 31;
    const int bn = blockIdx.x, bm = blockIdx.y;

    MmaAcc8 acc;
    #pragma unroll
    for (int i = 0; i < 2; i++)
        #pragma unroll
        for (int j = 0; j < 8; j++)
            #pragma unroll
            for (int q = 0; q < 4; q++) acc.a[i][j][q] = 0.f;

    mma_mainloop8(acc, sb, DD_ / 64, bm, bn, Ag, Bg, DD_, tid, wid, lane);

    const int wm = (wid & 3) * 32, wn = (wid >> 2) * 64;
    const int tig = lane & 3, gid = lane >> 2;
    #pragma unroll
    for (int mt = 0; mt < 2; mt++) {
        const int r0 = bm * 128 + wm + mt * 16 + gid;
        #pragma unroll
        for (int n8 = 0; n8 < 8; n8++) {
            const int cc = bn * 128 + wn + n8 * 8 + tig * 2;
            *reinterpret_cast<__nv_bfloat162*>(P + (size_t)r0 * NN_ + cc)
                = __floats2bfloat162_rn(acc.a[mt][n8][0], acc.a[mt][n8][1]);
            *reinterpret_cast<__nv_bfloat162*>(P + (size_t)(r0 + 8) * NN_ + cc)
                = __floats2bfloat162_rn(acc.a[mt][n8][2], acc.a[mt][n8][3]);
        }
    }
}

// ---------------- trunk GEMM with fused split epilogues ----------------------
template<int OSPL, bool RELU, bool HASADD>
__global__ void __launch_bounds__(512, 1) mma_gemm_kernel(
    const __nv_bfloat16* __restrict__ Ag, const __nv_bfloat16* __restrict__ Bg,
    const float* __restrict__ bias, const float* __restrict__ addend,
    float* __restrict__ C, __nv_bfloat16* __restrict__ S, int Ka)
{
    extern __shared__ char smem[];
    const uint32_t sb = smem_u32(smem);
    const int tid = threadIdx.x, wid = tid >> 5, lane = tid & 31;
    const int bn = blockIdx.x, bm = blockIdx.y;

    MmaAcc acc;
    #pragma unroll
    for (int i = 0; i < 2; i++)
        #pragma unroll
        for (int j = 0; j < 4; j++)
            #pragma unroll
            for (int q = 0; q < 4; q++) acc.a[i][j][q] = 0.f;

    mma_mainloop(acc, sb, Ka / 64, bm, bn, Ag, Bg, Ka, tid, wid, lane);

    const int wm = (wid & 3) * 32, wn = (wid >> 2) * 32;
    const int tig = lane & 3, gid = lane >> 2;
    #pragma unroll
    for (int mt = 0; mt < 2; mt++) {
        #pragma unroll
        for (int n8 = 0; n8 < 4; n8++) {
            const int cc = bn * 128 + wn + n8 * 8 + tig * 2;
            #pragma unroll
            for (int hh = 0; hh < 2; hh++) {
                const int r = bm * 128 + wm + mt * 16 + gid + hh * 8;
                #pragma unroll
                for (int e = 0; e < 2; e++) {
                    const int c = cc + e;
                    float v = acc.a[mt][n8][hh * 2 + e] + bias[c];
                    if (RELU)   v = fmaxf(v, 0.f);
                    if (HASADD) v += addend[(size_t)r * DD_ + c];
                    if (C) C[(size_t)r * DD_ + c] = v;
                    if (OSPL == 1) {
                        __nv_bfloat16 h = __float2bfloat16(v);
                        __nv_bfloat16 l = __float2bfloat16(v - __bfloat162float(h));
                        __nv_bfloat16* row = S + (size_t)r * KA3_;
                        row[c] = h; row[DD_ + c] = l; row[2*DD_ + c] = h;
                    }
                }
            }
        }
    }
}

// -------- fused head+tail GEMM: N=512, cols<256 -> eh/ehs, >=256 -> et/ets ----
__global__ void __launch_bounds__(512, 1) ht_gemm_kernel(
    const __nv_bfloat16* __restrict__ Ag, const __nv_bfloat16* __restrict__ Bg,
    const float* __restrict__ bhd, const float* __restrict__ btl,
    float* __restrict__ eh, float* __restrict__ et,
    __nv_bfloat16* __restrict__ ehs, __nv_bfloat16* __restrict__ ets)
{
    extern __shared__ char smem[];
    const uint32_t sb = smem_u32(smem);
    const int tid = threadIdx.x, wid = tid >> 5, lane = tid & 31;
    const int bn = blockIdx.x, bm = blockIdx.y;

    MmaAcc acc;
    #pragma unroll
    for (int i = 0; i < 2; i++)
        #pragma unroll
        for (int j = 0; j < 4; j++)
            #pragma unroll
            for (int q = 0; q < 4; q++) acc.a[i][j][q] = 0.f;

    mma_mainloop(acc, sb, KA3_ / 64, bm, bn, Ag, Bg, KA3_, tid, wid, lane);

    const int wm = (wid & 3) * 32, wn = (wid >> 2) * 32;
    const int tig = lane & 3, gid = lane >> 2;
    #pragma unroll
    for (int mt = 0; mt < 2; mt++) {
        #pragma unroll
        for (int n8 = 0; n8 < 4; n8++) {
            const int cc = bn * 128 + wn + n8 * 8 + tig * 2;
            #pragma unroll
            for (int hh = 0; hh < 2; hh++) {
                const int r = bm * 128 + wm + mt * 16 + gid + hh * 8;
                #pragma unroll
                for (int e = 0; e < 2; e++) {
                    const int c = cc + e;
                    if (c < 256) {
                        float v = acc.a[mt][n8][hh * 2 + e] + bhd[c];
                        eh [(size_t)r * DD_ + c] = v;
                        ehs[(size_t)r * DD_ + c] = __float2bfloat16(v * 0.0625f);
                    } else {
                        const int c2 = c - 256;
                        float v = acc.a[mt][n8][hh * 2 + e] + btl[c2];
                        et [(size_t)r * DD_ + c2] = v;
                        ets[(size_t)r * DD_ + c2] = __float2bfloat16(v);
                    }
                }
            }
        }
    }
}

// ---------------- per-row top-40 screening via 12-bit radix ------------------
// slot s = 8*j + e  ->  global idx = 8*(tid + j*256) + e
#define TK_CAP 512
__global__ void __launch_bounds__(256) topk_kernel(const __nv_bfloat16* __restrict__ P,
                                                   int* __restrict__ tI)
{
    const int row  = blockIdx.x;
    const int tid  = threadIdx.x;
    const int lane = tid & 31, w = tid >> 5;
    const uint4* p4 = reinterpret_cast<const uint4*>(P + (size_t)row * NN_);

    float v[32];
    uint32_t key[32];
    #pragma unroll
    for (int j = 0; j < 4; j++) {
        uint4 pk = p4[tid + j * 256];
        uint32_t ws[4] = {pk.x, pk.y, pk.z, pk.w};
        #pragma unroll
        for (int h = 0; h < 4; h++) {
            __nv_bfloat162 b2 = *reinterpret_cast<const __nv_bfloat162*>(&ws[h]);
            float2 f = __bfloat1622float2(b2);
            const int s = 8 * j + 2 * h;
            v[s]   = f.x;
            v[s+1] = f.y;
            uint32_t u0 = __float_as_uint(f.x);
            uint32_t u1 = __float_as_uint(f.y);
            key[s]   = (u0 & 0x80000000u) ? ~u0 : (u0 | 0x80000000u);
            key[s+1] = (u1 & 0x80000000u) ? ~u1 : (u1 | 0x80000000u);
        }
    }

    __shared__ int   hist[4096];
    __shared__ int   part[256];
    __shared__ int   wsum[8];
    __shared__ int   sPivot[4];
    __shared__ float sV[KS_];
    __shared__ int   sI[KS_];
    __shared__ float cV[TK_CAP];
    __shared__ int   cI[TK_CAP];
    __shared__ int   cnts[2];

    #pragma unroll
    for (int i = 0; i < 16; i++) hist[tid * 16 + i] = 0;
    if (tid < 2) cnts[tid] = 0;
    __syncthreads();

    #pragma unroll
    for (int s = 0; s < 32; s++) atomicAdd(&hist[key[s] >> 20], 1);
    __syncthreads();

    {
        int s = 0;
        #pragma unroll
        for (int i = 0; i < 16; i++) s += hist[tid * 16 + i];
        part[tid] = s;
    }
    __syncthreads();

    // parallel pivot selection (identical result to the serial descending scan)
    {
        const int rt = 255 - tid;            // descending region index
        const int vv = part[rt];
        // block-wide inclusive prefix over tid of vv  (= suffix sums of part)
        int pref = vv;
        #pragma unroll
        for (int off = 1; off < 32; off <<= 1) {
            int o = __shfl_up_sync(0xffffffffu, pref, off);
            if (lane >= off) pref += o;
        }
        if (lane == 31) wsum[w] = pref;
        __syncthreads();
        if (tid < 8) {
            int x = wsum[tid];
            #pragma unroll
            for (int off = 1; off < 8; off <<= 1) {
                int o = __shfl_up_sync(0xffu, x, off);
                if (tid >= off) x += o;
            }
            wsum[tid] = x;
        }
        __syncthreads();
        if (w > 0) pref += wsum[w - 1];
        // unique crossing thread: pref >= KS_ and pref - vv < KS_
        if (pref >= KS_ && pref - vv < KS_) {
            const int t = rt;
            int cntAbove = pref - vv;
            int b = -1;
            for (int bin = t * 16 + 15; bin >= t * 16; bin--) {
                int h = hist[bin];
                if (cntAbove + h >= KS_) { b = bin; break; }
                cntAbove += h;
            }
            sPivot[0] = b; sPivot[1] = cntAbove; sPivot[2] = 0;
        }
    }
    __syncthreads();

    const uint32_t pb = (uint32_t)sPivot[0];
    const int nAbove  = sPivot[1];

    #pragma unroll
    for (int s = 0; s < 32; s++) {
        uint32_t bin = key[s] >> 20;
        if (bin > pb) {
            int pos = atomicAdd(&cnts[0], 1);
            sV[pos] = v[s]; sI[pos] = 8 * (tid + (s >> 3) * 256) + (s & 7);
        } else if (bin == pb) {
            int pos = atomicAdd(&cnts[1], 1);
            if (pos < TK_CAP) { cV[pos] = v[s]; cI[pos] = 8 * (tid + (s >> 3) * 256) + (s & 7); }
            else sPivot[2] = 1;
        }
    }
    __syncthreads();

    if (sPivot[2] == 0) {
        if (tid < 32) {
            const int ncand = min(cnts[1], TK_CAP);
            const int need  = KS_ - nAbove;
            float mv[16]; int mi[16];
            #pragma unroll
            for (int q = 0; q < 16; q++) {
                int idx = tid + q * 32;
                if (idx < ncand) { mv[q] = cV[idx]; mi[q] = cI[idx]; }
                else             { mv[q] = -CUDART_INF_F; mi[q] = 0x7fffffff; }
            }
            for (int it = 0; it < need; it++) {
                float bv = mv[0]; int bi = mi[0], bq = 0;
                #pragma unroll
                for (int q = 1; q < 16; q++)
                    if (mv[q] > bv || (mv[q] == bv && mi[q] < bi)) { bv = mv[q]; bi = mi[q]; bq = q; }
                float wv = bv; int wi = bi;
                #pragma unroll
                for (int off = 16; off; off >>= 1) {
                    float ov = __shfl_xor_sync(0xffffffffu, wv, off);
                    int   oi = __shfl_xor_sync(0xffffffffu, wi, off);
                    if (ov > wv || (ov == wv && oi < wi)) { wv = ov; wi = oi; }
                }
                if (bi == wi && bv == wv && bi != 0x7fffffff) {
                    sI[nAbove + it] = wi;
                    mv[bq] = -CUDART_INF_F; mi[bq] = 0x7fffffff;
                }
                __syncwarp();
            }
        }
        __syncthreads();
    } else {
        // degenerate fallback: exact iterative argmax
        __syncthreads();
        __shared__ float fV[8]; __shared__ int fI[9];
        float bv = v[0]; int bs = 0;
        #pragma unroll
        for (int s = 1; s < 32; s++) if (v[s] > bv) { bv = v[s]; bs = s; }
        for (int it = 0; it < KS_; it++) {
            float wv = bv; int wi = 8 * (tid + (bs >> 3) * 256) + (bs & 7);
            #pragma unroll
            for (int off = 16; off; off >>= 1) {
                float ov = __shfl_xor_sync(0xffffffffu, wv, off);
                int   oi = __shfl_xor_sync(0xffffffffu, wi, off);
                if (ov > wv || (ov == wv && oi < wi)) { wv = ov; wi = oi; }
            }
            if (lane == 0) { fV[w] = wv; fI[w] = wi; }
            __syncthreads();
            if (tid == 0) {
                float Bv = fV[0]; int Bi = fI[0];
                #pragma unroll
                for (int q = 1; q < 8; q++)
                    if (fV[q] > Bv || (fV[q] == Bv && fI[q] < Bi)) { Bv = fV[q]; Bi = fI[q]; }
                sI[it] = Bi; fI[8] = Bi;
            }
            __syncthreads();
            const int win = fI[8];
            if (((win >> 3) & 255) == tid) {
                v[8 * (win >> 11) + (win & 7)] = -CUDART_INF_F;
                bv = v[0]; bs = 0;
                #pragma unroll
                for (int s = 1; s < 32; s++) if (v[s] > bv) { bv = v[s]; bs = s; }
            }
        }
        __syncthreads();
    }

    if (tid < KS_) tI[row * KS_ + tid] = sI[tid];
}

// ------ fused rescore + parallel-rank exact top-30 + neighbor aggregation ----
__global__ void __launch_bounds__(256) neighbor_kernel(
    const float* __restrict__ eH, const float* __restrict__ eT,
    const int* __restrict__ tI,
    __nv_bfloat16* __restrict__ Ub, __nv_bfloat16* __restrict__ Vb)
{
    const int row  = blockIdx.x;
    const int d    = threadIdx.x;
    const int lane = d & 31, w = d >> 5;

    __shared__ __align__(16) float sNb[KS_][DD_];
    __shared__ __align__(16) float sEh[DD_];
    __shared__ float sVal[KS_];
    __shared__ int   sIdx[KS_];
    __shared__ int   sSel[KT_];
    __shared__ float sSelV[KT_];
    __shared__ float sPr[KT_];
    __shared__ float sW[KT_];
    __shared__ float sKa[KT_];

    const float eh = eH[(size_t)row * DD_ + d];
    sEh[d] = eh;
    if (d < KS_) sIdx[d] = tI[row * KS_ + d];
    __syncthreads();

    // batched gather: each warp owns rows w, w+8, ..., w+32 (all 10 LDG.128 in flight)
    float4 t0[5], t1[5];
    #pragma unroll
    for (int i = 0; i < 5; i++) {
        const int k = w + i * 8;
        const float4* src = reinterpret_cast<const float4*>(eT + (size_t)sIdx[k] * DD_);
        t0[i] = src[lane];
        t1[i] = src[lane + 32];
    }
    {
        const float4* eh4 = reinterpret_cast<const float4*>(sEh);
        #pragma unroll
        for (int i = 0; i < 5; i++) {
            const int k = w + i * 8;
            float4* dst = reinterpret_cast<float4*>(sNb[k]);
            dst[lane] = t0[i];
            dst[lane + 32] = t1[i];
            float dot = 0.f;
            {
                float4 t = t0[i]; float4 e4 = eh4[lane];
                dot += t.x * e4.x + t.y * e4.y + t.z * e4.z + t.w * e4.w;
            }
            {
                float4 t = t1[i]; float4 e4 = eh4[lane + 32];
                dot += t.x * e4.x + t.y * e4.y + t.z * e4.z + t.w * e4.w;
            }
            #pragma unroll
            for (int off = 16; off; off >>= 1) dot += __shfl_xor_sync(0xffffffffu, dot, off);
            if (lane == 0) sVal[k] = dot * 0.0625f;
        }
    }
    __syncthreads();

    // parallel rank select: exact top-30-of-40 by (value desc, idx asc)
    if (d < KS_) {
        const float vd = sVal[d];
        const int   id = sIdx[d];
        int rank = 0;
        #pragma unroll
        for (int j = 0; j < KS_; j++) {
            const float vj = sVal[j];
            const int   ij = sIdx[j];
            if (vj > vd || (vj == vd && ij < id)) rank++;
        }
        if (rank < KT_) { sSel[rank] = d; sSelV[rank] = vd; }
    }
    __syncthreads();

    if (d < 32) {
        float ev = (d < KT_) ? expf(sSelV[d] - sSelV[0]) : 0.f;
        float s = ev;
        #pragma unroll
        for (int off = 16; off; off >>= 1) s += __shfl_xor_sync(0xffffffffu, s, off);
        if (d < KT_) sPr[d] = ev / s;
    }
    __syncthreads();

    for (int k = w; k < KT_; k += 8) {
        const int s = sSel[k];
        const float pk = sPr[k], ck = 2.f - pk;
        float snb = 0.f, sg = 0.f;
        #pragma unroll
        for (int q = 0; q < 8; q++) {
            const int dd = lane + q * 32;
            const float nb = sNb[s][dd];
            snb += nb;
            sg  += tanhf(ck * sEh[dd] + pk * nb);
        }
        #pragma unroll
        for (int off = 16; off; off >>= 1) {
            snb += __shfl_xor_sync(0xffffffffu, snb, off);
            sg  += __shfl_xor_sync(0xffffffffu, sg,  off);
        }
        if (lane == 0) sW[k] = snb * sg;
    }
    __syncthreads();

    if (d < 32) {
        float val = (d < KT_) ? sW[d] : -CUDART_INF_F;
        float m = val;
        #pragma unroll
        for (int off = 16; off; off >>= 1) m = fmaxf(m, __shfl_xor_sync(0xffffffffu, m, off));
        float ev = (d < KT_) ? expf(val - m) : 0.f;
        float s = ev;
        #pragma unroll
        for (int off = 16; off; off >>= 1) s += __shfl_xor_sync(0xffffffffu, s, off);
        if (d < KT_) sKa[d] = ev / s;
    }
    __syncthreads();

    float acc = 0.f;
    #pragma unroll
    for (int k = 0; k < KT_; k++) acc += sKa[k] * sNb[sSel[k]][d];

    const float u = eh + acc, vv = eh * acc;
    {
        __nv_bfloat16 h = __float2bfloat16(u);
        __nv_bfloat16 l = __float2bfloat16(u - __bfloat162float(h));
        __nv_bfloat16* rw = Ub + (size_t)row * KA3_;
        rw[d] = h; rw[DD_ + d] = l; rw[2*DD_ + d] = h;
    }
    {
        __nv_bfloat16 h = __float2bfloat16(vv);
        __nv_bfloat16 l = __float2bfloat16(vv - __bfloat162float(h));
        __nv_bfloat16* rw = Vb + (size_t)row * KA3_;
        rw[d] = h; rw[DD_ + d] = l; rw[2*DD_ + d] = h;
    }
}

// ---------------- attention head ----------------------------------------------
__global__ void __launch_bounds__(128) att_kernel(
    const float* __restrict__ E, const float* __restrict__ W1,
    const float* __restrict__ b1, const float* __restrict__ W2,
    const float* __restrict__ b2, float* __restrict__ att)
{
    const int r0 = blockIdx.x * 16;
    const int j  = threadIdx.x;
    __shared__ float sE[16][DD_];
    for (int t = j; t < 16 * DD_; t += 128)
        sE[t >> 8][t & 255] = E[(size_t)(r0 + (t >> 8)) * DD_ + (t & 255)];
    __syncthreads();

    float acc[16];
    #pragma unroll
    for (int r = 0; r < 16; r++) acc[r] = 0.f;
    for (int dd = 0; dd < DD_; dd++) {
        const float wv = W1[dd * 128 + j];
        #pragma unroll
        for (int r = 0; r < 16; r++) acc[r] += sE[r][dd] * wv;
    }
    const float bb = b1[j], w2 = W2[j];
    __shared__ float sRed[16][4];
    const int lane = j & 31, w = j >> 5;
    #pragma unroll
    for (int r = 0; r < 16; r++) {
        float val = acc[r] + bb;
        val = (val > 0.f) ? val : 0.01f * val;
        val *= w2;
        #pragma unroll
        for (int off = 16; off; off >>= 1) val += __shfl_xor_sync(0xffffffffu, val, off);
        if (lane == 0) sRed[r][w] = val;
    }
    __syncthreads();
    if (j < 16) att[r0 + j] = sRed[j][0] + sRed[j][1] + sRed[j][2] + sRed[j][3] + b2[0];
}

// ---------------- softmax-over-nodes reduction --------------------------------
__global__ void __launch_bounds__(1024) smred_kernel(const float* __restrict__ att,
                                                     float* __restrict__ red)
{
    const int tid = threadIdx.x;
    __shared__ float s[32];
    float m = -CUDART_INF_F;
    for (int i = tid; i < NN_; i += 1024) m = fmaxf(m, att[i]);
    #pragma unroll
    for (int off = 16; off; off >>= 1) m = fmaxf(m, __shfl_xor_sync(0xffffffffu, m, off));
    if ((tid & 31) == 0) s[tid >> 5] = m;
    __syncthreads();
    if (tid < 32) {
        float mm = s[tid];
        #pragma unroll
        for (int off = 16; off; off >>= 1) mm = fmaxf(mm, __shfl_xor_sync(0xffffffffu, mm, off));
        if (tid == 0) s[0] = mm;
    }
    __syncthreads();
    const float M = s[0];
    __syncthreads();
    float z = 0.f;
    for (int i = tid; i < NN_; i += 1024) z += expf(att[i] - M);
    #pragma unroll
    for (int off = 16; off; off >>= 1) z += __shfl_xor_sync(0xffffffffu, z, off);
    if ((tid & 31) == 0) s[tid >> 5] = z;
    __syncthreads();
    if (tid < 32) {
        float zz = s[tid];
        #pragma unroll
        for (int off = 16; off; off >>= 1) zz += __shfl_xor_sync(0xffffffffu, zz, off);
        if (tid == 0) { red[0] = M; red[1] = zz; }
    }
}

__global__ void __launch_bounds__(256) egpart_kernel(const float* __restrict__ att,
    const float* __restrict__ E, const float* __restrict__ red, float* __restrict__ part)
{
    const int b = blockIdx.x;
    const int d = threadIdx.x;
    __shared__ float wsh[256];
    wsh[d] = expf(att[b * 256 + d] - red[0]);
    __syncthreads();
    float acc = 0.f;
    const float* Eb = E + (size_t)b * 256 * DD_;
    for (int i = 0; i < 256; i++) acc += wsh[i] * Eb[(size_t)i * DD_ + d];
    part[b * DD_ + d] = acc;
}

__global__ void __launch_bounds__(256) egfin_kernel(const float* __restrict__ part,
    const float* __restrict__ red, float* __restrict__ eg)
{
    const int d = threadIdx.x;
    float s = 0.f;
    #pragma unroll
    for (int b = 0; b < 32; b++) s += part[b * DD_ + d];
    eg[d] = s / red[1];
}

// ---------------- launcher -----------------------------------------------------
extern "C" void kernel_launch(void* const* d_in, const int* in_sizes, int n_in,
                              void* d_out, int out_size)
{
    const float* x    = (const float*)d_in[0];
    const float* Wfc1 = (const float*)d_in[1];
    const float* bfc1 = (const float*)d_in[2];
    const float* Wfc2 = (const float*)d_in[3];
    const float* bfc2 = (const float*)d_in[4];
    const float* Whd  = (const float*)d_in[5];
    const float* bhd  = (const float*)d_in[6];
    const float* Wtl  = (const float*)d_in[7];
    const float* btl  = (const float*)d_in[8];
    const float* Wl1  = (const float*)d_in[9];
    const float* bl1  = (const float*)d_in[10];
    const float* Wl2  = (const float*)d_in[11];
    const float* bl2  = (const float*)d_in[12];
    const float* Wa1  = (const float*)d_in[13];
    const float* ba1  = (const float*)d_in[14];
    const float* Wa2  = (const float*)d_in[15];
    const float* ba2  = (const float*)d_in[16];

    float *eh, *et, *E1, *spill, *att, *red, *part;
    __nv_bfloat16 *P, *Xbf, *h1b, *hb, *ehs, *ets, *Ub, *Vb;
    __nv_bfloat16 *Wfc1b, *Wfc2b, *Whtb, *Wl1b, *Wl2b;
    int* tI;
    cudaGetSymbolAddress((void**)&P,     g_P);
    cudaGetSymbolAddress((void**)&eh,    g_eh);
    cudaGetSymbolAddress((void**)&et,    g_et);
    cudaGetSymbolAddress((void**)&E1,    g_E1);
    cudaGetSymbolAddress((void**)&spill, g_spill);
    cudaGetSymbolAddress((void**)&att,   g_att);
    cudaGetSymbolAddress((void**)&red,   g_red);
    cudaGetSymbolAddress((void**)&part,  g_part);
    cudaGetSymbolAddress((void**)&tI,    g_tI);
    cudaGetSymbolAddress((void**)&Xbf,   g_Xbf);
    cudaGetSymbolAddress((void**)&h1b,   g_h1b);
    cudaGetSymbolAddress((void**)&hb,    g_hb);
    cudaGetSymbolAddress((void**)&ehs,   g_ehs);
    cudaGetSymbolAddress((void**)&ets,   g_ets);
    cudaGetSymbolAddress((void**)&Ub,    g_Ub);
    cudaGetSymbolAddress((void**)&Vb,    g_Vb);
    cudaGetSymbolAddress((void**)&Wfc1b, g_Wfc1b);
    cudaGetSymbolAddress((void**)&Wfc2b, g_Wfc2b);
    cudaGetSymbolAddress((void**)&Whtb,  g_Whtb);
    cudaGetSymbolAddress((void**)&Wl1b,  g_Wl1b);
    cudaGetSymbolAddress((void**)&Wl2b,  g_Wl2b);

    const int smemNeed = 3 * MMA_STG;
    cudaFuncSetAttribute(attn_mma_kernel,
                         cudaFuncAttributeMaxDynamicSharedMemorySize, smemNeed);
    cudaFuncSetAttribute(ht_gemm_kernel,
                         cudaFuncAttributeMaxDynamicSharedMemorySize, smemNeed);
    cudaFuncSetAttribute(mma_gemm_kernel<1, true,  false>,
                         cudaFuncAttributeMaxDynamicSharedMemorySize, smemNeed);
    cudaFuncSetAttribute(mma_gemm_kernel<0, true,  false>,
                         cudaFuncAttributeMaxDynamicSharedMemorySize, smemNeed);
    cudaFuncSetAttribute(mma_gemm_kernel<0, true,  true>,
                         cudaFuncAttributeMaxDynamicSharedMemorySize, smemNeed);

    float* out = (float*)d_out;
    const size_t ND = (size_t)NN_ * DD_;
    float* e_out;
    float* eg_out;
    if ((size_t)out_size >= ND + DD_)      { e_out = out;   eg_out = out + ND; }
    else if ((size_t)out_size >= ND)       { e_out = out;   eg_out = nullptr;  }
    else                                   { e_out = spill; eg_out = out;      }

    const dim3 gG(2, 64);
    const dim3 gHT(4, 64);
    const dim3 gA(64, 64);

    xsplit_kernel<<<NN_, 256>>>(x, Xbf);
    wprep6_kernel<<<DIN_ + 5 * DD_, 256>>>(Wfc1, Wfc2, Whd, Wtl, Wl1, Wl2,
                                           Wfc1b, Wfc2b, Whtb, Whtb + 256 * KA3_,
                                           Wl1b, Wl2b);

    mma_gemm_kernel<1, true, false><<<gG, 512, smemNeed>>>(Xbf, Wfc1b, bfc1, nullptr, nullptr, h1b, KAX3_);
    mma_gemm_kernel<1, true, false><<<gG, 512, smemNeed>>>(h1b, Wfc2b, bfc2, nullptr, nullptr, hb,  KA3_);
    ht_gemm_kernel<<<gHT, 512, smemNeed>>>(hb, Whtb, bhd, btl, eh, et, ehs, ets);

    attn_mma_kernel<<<gA, 256, smemNeed>>>(ehs, ets, P);
    topk_kernel    <<<NN_, 256>>>(P, tI);
    neighbor_kernel<<<NN_, 256>>>(eh, et, tI, Ub, Vb);

    mma_gemm_kernel<0, true, false><<<gG, 512, smemNeed>>>(Ub, Wl1b, bl1, nullptr, E1,    nullptr, KA3_);
    mma_gemm_kernel<0, true, true ><<<gG, 512, smemNeed>>>(Vb, Wl2b, bl2, E1,      e_out, nullptr, KA3_);

    if (eg_out) {
        att_kernel   <<<NN_ / 16, 128>>>(e_out, Wa1, ba1, Wa2, ba2, att);
        smred_kernel <<<1, 1024>>>(att, red);
        egpart_kernel<<<32, 256>>>(att, e_out, red, part);
        egfin_kernel <<<1, 256>>>(part, red, eg_out);
    }
}